// round 1
// baseline (speedup 1.0000x reference)
#include <cuda_runtime.h>
#include <math.h>

#define NB 16
#define NC 96
#define NR 4
#define NO 48
#define NH 66
#define NHW (NH*NH)          // 4356
#define NCR (NC*NR)          // 384
#define HO 64
#define BN_EPS 2e-5f
#define NPIX_PER_CH (NB*NR*NHW)  // 278784

// ---------------- scratch (device globals; no allocations allowed) ----------------
__device__ float d_psum[NC*8];
__device__ float d_psq[NC*8];
__device__ float d_ga[NC];
__device__ float d_gb[NC];
__device__ float d_savg[NB*NCR];
__device__ float d_smax[NB*NCR];
__device__ float d_ca[NB*NR*NCR];          // [b][h][cr]
__device__ float d_um[NB*NR*NHW];          // channel-mean pooled  [b*4+r][hw]
__device__ float d_ux[NB*NR*NHW];          // channel-max pooled
__device__ float d_sp[NB*NR*NHW];          // spatial attention    [b*4+h][hw]
__device__ float d_wt[NR*NCR*9*NO];        // transformed conv weights [h][cr][ij][o]
__device__ float d_wsa[NR*2*NR*49];        // transformed sa weights   [h][p][r][ij]

__device__ __forceinline__ float warpSum(float v) {
    #pragma unroll
    for (int o = 16; o; o >>= 1) v += __shfl_down_sync(0xffffffffu, v, o);
    return v;
}
__device__ __forceinline__ float warpMax(float v) {
    #pragma unroll
    for (int o = 16; o; o >>= 1) v = fmaxf(v, __shfl_down_sync(0xffffffffu, v, o));
    return v;
}
__device__ __forceinline__ float sigmoidf(float v) {
    return 1.f / (1.f + expf(-v));
}

// ---------------- 1) BN statistics, stage 1 (deterministic, no atomics) -----------
__global__ void k_stats(const float* __restrict__ x) {
    int c = blockIdx.x, part = blockIdx.y, tid = threadIdx.x;
    float s = 0.f, q = 0.f;
    #pragma unroll
    for (int b2 = 0; b2 < 2; b2++) {
        const float4* p4 = (const float4*)(x + (size_t)((part*2 + b2)*NC + c) * (NR*NHW));
        for (int i = tid; i < NR*NHW/4; i += 256) {
            float4 v = p4[i];
            s += v.x + v.y + v.z + v.w;
            q += v.x*v.x + v.y*v.y + v.z*v.z + v.w*v.w;
        }
    }
    __shared__ float rs[8], rq[8];
    int wid = tid >> 5, lane = tid & 31;
    s = warpSum(s); q = warpSum(q);
    if (lane == 0) { rs[wid] = s; rq[wid] = q; }
    __syncthreads();
    if (tid == 0) {
        float S = 0.f, Q = 0.f;
        #pragma unroll
        for (int j = 0; j < 8; j++) { S += rs[j]; Q += rq[j]; }
        d_psum[c*8 + part] = S;
        d_psq [c*8 + part] = Q;
    }
}

// ---------------- 2) BN finalize: fold into per-channel affine --------------------
__global__ void k_finalize(const float* __restrict__ gamma, const float* __restrict__ beta) {
    int c = threadIdx.x;
    if (c >= NC) return;
    float s = 0.f, q = 0.f;
    #pragma unroll
    for (int j = 0; j < 8; j++) { s += d_psum[c*8+j]; q += d_psq[c*8+j]; }
    float mean = s * (1.f / NPIX_PER_CH);
    float var  = q * (1.f / NPIX_PER_CH) - mean*mean;
    float inv  = rsqrtf(var + BN_EPS);
    float a = gamma[c] * inv;
    d_ga[c] = a;
    d_gb[c] = beta[c] - mean * a;
}

// ---------------- 3) transform conv weights: Wt[h][cr][ij][o] ---------------------
__global__ void k_wt(const float* __restrict__ cw) {
    int idx = blockIdx.x*256 + threadIdx.x;
    if (idx >= NR*NCR*9*NO) return;
    int o  = idx % NO;  int t = idx / NO;
    int ij = t % 9;     t /= 9;
    int cr = t % NCR;   int h = t / NCR;
    int i = ij / 3, j = ij % 3;
    int c = cr >> 2, r = cr & 3;
    int rs = (r - h) & 3;
    int si, sj;
    switch (h) {
        case 0:  si = i;     sj = j;     break;
        case 1:  si = j;     sj = 2 - i; break;
        case 2:  si = 2 - i; sj = 2 - j; break;
        default: si = 2 - j; sj = i;     break;
    }
    d_wt[idx] = cw[(((o*NC + c)*NR + rs)*3 + si)*3 + sj];
}

// ---------------- 4) transform spatial-attention weights --------------------------
__global__ void k_wsa(const float* __restrict__ sw) {
    int idx = blockIdx.x*256 + threadIdx.x;
    if (idx >= NR*2*NR*49) return;
    int ij = idx % 49; int t = idx / 49;
    int r  = t & 3;    t >>= 2;
    int p  = t & 1;    int h = t >> 1;
    int i = ij / 7, j = ij % 7;
    int rs = (r - h) & 3;
    int si, sj;
    switch (h) {
        case 0:  si = i;     sj = j;     break;
        case 1:  si = j;     sj = 6 - i; break;
        case 2:  si = 6 - i; sj = 6 - j; break;
        default: si = 6 - j; sj = i;     break;
    }
    d_wsa[idx] = sw[(p*NR + rs)*49 + si*7 + sj];
}

// ---------------- 5) spatial squeeze: s_avg / s_max per (b,c,r) -------------------
__global__ void k_pool_scr(const float* __restrict__ x) {
    int id = blockIdx.x;                 // (b*96+c)*4+r  == b*384 + cr
    int c = (id >> 2) % NC;
    int tid = threadIdx.x;
    const float* p = x + (size_t)id * NHW;
    float ga = d_ga[c], gb = d_gb[c];
    float s = 0.f, m = 0.f;
    for (int i = tid; i < NHW; i += 256) {
        float v = fmaxf(fmaf(ga, p[i], gb), 0.f);
        s += v; m = fmaxf(m, v);
    }
    __shared__ float rs[8], rm[8];
    int wid = tid >> 5, lane = tid & 31;
    s = warpSum(s); m = warpMax(m);
    if (lane == 0) { rs[wid] = s; rm[wid] = m; }
    __syncthreads();
    if (tid == 0) {
        float S = 0.f, M = 0.f;
        #pragma unroll
        for (int j = 0; j < 8; j++) { S += rs[j]; M = fmaxf(M, rm[j]); }
        d_savg[id] = S * (1.f / NHW);
        d_smax[id] = M;
    }
}

// ---------------- 6) channel pooling: mean/max over C per (b,r,pixel) -------------
__global__ void k_pool_ch(const float* __restrict__ x) {
    __shared__ float sga[NC], sgb[NC];
    int tid = threadIdx.x;
    if (tid < NC) { sga[tid] = d_ga[tid]; sgb[tid] = d_gb[tid]; }
    __syncthreads();
    int br = blockIdx.y;               // b*4 + r
    int b = br >> 2, r = br & 3;
    int p = blockIdx.x*256 + tid;
    if (p >= NHW) return;
    float s = 0.f, m = 0.f;
    const float* xb = x + (size_t)(b*NCR + r) * NHW + p;
    #pragma unroll 4
    for (int c = 0; c < NC; c++) {
        float v = fmaxf(fmaf(sga[c], xb[(size_t)(c*4) * NHW], sgb[c]), 0.f);
        s += v; m = fmaxf(m, v);
    }
    d_um[br*NHW + p] = s * (1.f / NC);
    d_ux[br*NHW + p] = m;
}

// ---------------- 7) channel attention MLP (tiny) ---------------------------------
__global__ void k_chatt(const float* __restrict__ fc1, const float* __restrict__ fc2) {
    int b = blockIdx.x, tid = threadIdx.x;
    __shared__ float sA[NCR], sM[NCR], f1[2*NCR], f2[NC*8];
    __shared__ float dred[16], hsum[8];
    for (int i = tid; i < NCR; i += 256) { sA[i] = d_savg[b*NCR + i]; sM[i] = d_smax[b*NCR + i]; }
    for (int i = tid; i < 2*NCR; i += 256) { f1[i] = fc1[i]; f2[i] = fc2[i]; }
    __syncthreads();
    int wid = tid >> 5, lane = tid & 31;
    #pragma unroll
    for (int dd = 0; dd < 2; dd++) {
        int d = wid*2 + dd;               // d = ((h*2+e)*2 + sel)
        int sel = d & 1, he = d >> 1;
        int h = he >> 1, e = he & 1;
        const float* sv = sel ? sM : sA;
        float sum = 0.f;
        for (int k = lane; k < NCR; k += 32) {
            int r = k & 3;
            sum += sv[k] * f1[e*NCR + (k & ~3) + (((r - h) & 3))];
        }
        sum = warpSum(sum);
        if (lane == 0) dred[d] = fmaxf(sum, 0.f);   // relu
    }
    __syncthreads();
    if (tid < 8) hsum[tid] = dred[tid*2] + dred[tid*2 + 1];
    __syncthreads();
    for (int idx = tid; idx < NR*NCR; idx += 256) {
        int h = idx / NCR, cr = idx % NCR;
        int c = cr >> 2, r = cr & 3;
        int rs = (r - h) & 3;
        float v = hsum[h*2 + 0] * f2[c*8 + rs]
                + hsum[h*2 + 1] * f2[c*8 + 4 + rs];
        d_ca[b*(NR*NCR) + idx] = sigmoidf(v);
    }
}

// ---------------- 8) spatial attention: 7x7 group conv over pooled maps -----------
__global__ void k_spatt() {
    __shared__ float ws[2*NR*49];
    int tid = threadIdx.x;
    int bh = blockIdx.y;                // b*4 + h
    int b = bh >> 2, h = bh & 3;
    for (int i = tid; i < 2*NR*49; i += 256) ws[i] = d_wsa[h*(2*NR*49) + i];
    __syncthreads();
    int p = blockIdx.x*256 + tid;
    if (p >= NHW) return;
    int y = p / NH, x0 = p % NH;
    float s = 0.f;
    #pragma unroll
    for (int p2 = 0; p2 < 2; p2++) {
        const float* ubase = p2 ? d_ux : d_um;
        #pragma unroll
        for (int r = 0; r < NR; r++) {
            const float* u = ubase + (size_t)(b*4 + r) * NHW;
            const float* w = ws + (p2*4 + r)*49;
            #pragma unroll
            for (int i = 0; i < 7; i++) {
                int Y = y + i - 3;
                if (Y < 0 || Y >= NH) continue;
                #pragma unroll
                for (int j = 0; j < 7; j++) {
                    int X = x0 + j - 3;
                    if (X < 0 || X >= NH) continue;
                    s += u[Y*NH + X] * w[i*7 + j];
                }
            }
        }
    }
    d_sp[bh*NHW + p] = sigmoidf(s);
}

// ---------------- 9) the big gated group conv (O=48, K=384*9, 64x64 out) ----------
__global__ __launch_bounds__(256, 2) void k_conv(const float* __restrict__ x,
                                                 float* __restrict__ out) {
    int bh = blockIdx.z;                // b*4 + h
    int b = bh >> 2, h = bh & 3;
    int ox0 = blockIdx.x * 32, oy0 = blockIdx.y * 8;
    int tid = threadIdx.x, tx = tid & 31, ty = tid >> 5;

    __shared__ float s_in[8][10][34];
    __shared__ __align__(16) float s_w[8*9*48];
    __shared__ float s_sp[10][34];
    __shared__ float s_ga[NCR], s_gb[NCR];

    for (int i = tid; i < 340; i += 256) {
        int row = i / 34, col = i % 34;
        s_sp[row][col] = d_sp[bh*NHW + (oy0 + row)*NH + ox0 + col];
    }
    for (int i = tid; i < NCR; i += 256) {
        float ca = d_ca[bh*NCR + i];          // sigmoid>0: fold through relu
        int c = i >> 2;
        s_ga[i] = d_ga[c] * ca;
        s_gb[i] = d_gb[c] * ca;
    }

    float acc[48];
    #pragma unroll
    for (int o = 0; o < 48; o++) acc[o] = 0.f;

    const float* xb = x + (size_t)b * NCR * NHW;

    for (int k = 0; k < 48; k++) {
        int cr0 = k * 8;
        __syncthreads();
        const float4* wsrc = (const float4*)(d_wt + (size_t)(h*NCR + cr0) * 432);
        #pragma unroll 4
        for (int i = tid; i < 864; i += 256) ((float4*)s_w)[i] = wsrc[i];
        #pragma unroll 1
        for (int i = tid; i < 2720; i += 256) {
            int g = i / 340; int rem = i - g*340;
            int row = rem / 34; int col = rem - row*34;
            int cr = cr0 + g;
            float v = xb[(size_t)cr * NHW + (oy0 + row)*NH + ox0 + col];
            v = fmaxf(fmaf(s_ga[cr], v, s_gb[cr]), 0.f) * s_sp[row][col];
            s_in[g][row][col] = v;
        }
        __syncthreads();
        #pragma unroll 1
        for (int g = 0; g < 8; g++) {
            float iv[9];
            #pragma unroll
            for (int ii = 0; ii < 3; ii++)
                #pragma unroll
                for (int jj = 0; jj < 3; jj++)
                    iv[ii*3 + jj] = s_in[g][ty + ii][tx + jj];
            const float* wg = s_w + g*432;
            #pragma unroll
            for (int p = 0; p < 9; p++) {
                #pragma unroll
                for (int o4 = 0; o4 < 12; o4++) {
                    float4 w = *(const float4*)(wg + p*48 + o4*4);
                    acc[o4*4 + 0] = fmaf(iv[p], w.x, acc[o4*4 + 0]);
                    acc[o4*4 + 1] = fmaf(iv[p], w.y, acc[o4*4 + 1]);
                    acc[o4*4 + 2] = fmaf(iv[p], w.z, acc[o4*4 + 2]);
                    acc[o4*4 + 3] = fmaf(iv[p], w.w, acc[o4*4 + 3]);
                }
            }
        }
    }

    size_t obase = (((size_t)b*144)*4 + h)*4096 + (size_t)(oy0 + ty)*64 + (ox0 + tx);
    #pragma unroll
    for (int o = 0; o < 48; o++)
        out[obase + (size_t)o * 4 * 4096] = acc[o];
}

// ---------------- 10) dense concat: crop x into out channels 48..143 --------------
__global__ void k_crop(const float* __restrict__ x, float* __restrict__ out) {
    int idx = blockIdx.x*256 + threadIdx.x;   // over B*C*R*64*16 float4 stores
    if (idx >= NB*NC*NR*64*16) return;
    int q   = idx & 15;
    int y   = (idx >> 4) & 63;
    int brc = idx >> 10;                      // (b*96+c)*4+r
    int b   = brc / NCR;
    int crr = brc % NCR;
    int c   = crr >> 2, r = crr & 3;
    const float* src = x + (size_t)brc * NHW + (size_t)(y + 1)*NH + (q*4 + 1);
    float4 v = make_float4(src[0], src[1], src[2], src[3]);
    size_t off = (((size_t)b*144 + 48 + c)*4 + r)*4096 + (size_t)y*64 + q*4;
    *(float4*)(out + off) = v;
}

// ---------------- launch ----------------------------------------------------------
extern "C" void kernel_launch(void* const* d_in, const int* in_sizes, int n_in,
                              void* d_out, int out_size) {
    const float* x     = (const float*)d_in[0];
    const float* gamma = (const float*)d_in[1];
    const float* beta  = (const float*)d_in[2];
    const float* fc1   = (const float*)d_in[3];
    const float* fc2   = (const float*)d_in[4];
    const float* sa    = (const float*)d_in[5];
    const float* cw    = (const float*)d_in[6];
    float* out = (float*)d_out;
    (void)in_sizes; (void)n_in; (void)out_size;

    k_stats   <<<dim3(NC, 8), 256>>>(x);
    k_finalize<<<1, 128>>>(gamma, beta);
    k_wt      <<<(NR*NCR*9*NO + 255)/256, 256>>>(cw);
    k_wsa     <<<(NR*2*NR*49 + 255)/256, 256>>>(sa);
    k_pool_scr<<<NB*NCR, 256>>>(x);
    k_pool_ch <<<dim3((NHW + 255)/256, NB*NR), 256>>>(x);
    k_chatt   <<<NB, 256>>>(fc1, fc2);
    k_spatt   <<<dim3((NHW + 255)/256, NB*NR), 256>>>();
    k_conv    <<<dim3(2, 8, NB*NR), 256>>>(x, out);
    k_crop    <<<(NB*NC*NR*64*16 + 255)/256, 256>>>(x, out);
}

// round 2
// speedup vs baseline: 1.0237x; 1.0237x over previous
#include <cuda_runtime.h>
#include <math.h>

#define NB 16
#define NC 96
#define NR 4
#define NO 48
#define NH 66
#define NHW (NH*NH)          // 4356
#define NCR (NC*NR)          // 384
#define HO 64
#define BN_EPS 2e-5f
#define NPIX_PER_CH (NB*NR*NHW)  // 278784

// ---------------- scratch (device globals; no allocations allowed) ----------------
__device__ float d_psum[NC*8];
__device__ float d_psq[NC*8];
__device__ float d_ga[NC];
__device__ float d_gb[NC];
__device__ float d_savg[NB*NCR];
__device__ float d_smax[NB*NCR];
__device__ float d_ca[NB*NR*NCR];          // [b][h][cr]
__device__ float d_um[NB*NR*NHW];          // channel-mean pooled  [b*4+r][hw]
__device__ float d_ux[NB*NR*NHW];          // channel-max pooled
__device__ float d_sp[NB*NR*NHW];          // spatial attention    [b*4+h][hw]
__device__ float d_wt[NR*NCR*9*NO];        // transformed conv weights [h][cr][ij][o]
__device__ float d_wsa[NR*2*NR*49];        // transformed sa weights   [h][p][r][ij]

__device__ __forceinline__ float warpSum(float v) {
    #pragma unroll
    for (int o = 16; o; o >>= 1) v += __shfl_down_sync(0xffffffffu, v, o);
    return v;
}
__device__ __forceinline__ float warpMax(float v) {
    #pragma unroll
    for (int o = 16; o; o >>= 1) v = fmaxf(v, __shfl_down_sync(0xffffffffu, v, o));
    return v;
}
__device__ __forceinline__ float sigmoidf(float v) {
    return 1.f / (1.f + expf(-v));
}

// packed f32x2 FMA: d = a*b + d  (per-32-bit-lane fp32, exact)
#define FFMA2(d, a, b) asm("fma.rn.f32x2 %0, %1, %2, %0;" : "+l"(d) : "l"(a), "l"(b))
#define PACK2(d, lo, hi) asm("mov.b64 %0, {%1, %2};" : "=l"(d) : "r"(lo), "r"(hi))
#define UNPACK2(lo, hi, s) asm("mov.b64 {%0, %1}, %2;" : "=r"(lo), "=r"(hi) : "l"(s))

// ---------------- 1) BN statistics, stage 1 (deterministic, no atomics) -----------
__global__ void k_stats(const float* __restrict__ x) {
    int c = blockIdx.x, part = blockIdx.y, tid = threadIdx.x;
    float s = 0.f, q = 0.f;
    #pragma unroll
    for (int b2 = 0; b2 < 2; b2++) {
        const float4* p4 = (const float4*)(x + (size_t)((part*2 + b2)*NC + c) * (NR*NHW));
        for (int i = tid; i < NR*NHW/4; i += 256) {
            float4 v = p4[i];
            s += v.x + v.y + v.z + v.w;
            q += v.x*v.x + v.y*v.y + v.z*v.z + v.w*v.w;
        }
    }
    __shared__ float rs[8], rq[8];
    int wid = tid >> 5, lane = tid & 31;
    s = warpSum(s); q = warpSum(q);
    if (lane == 0) { rs[wid] = s; rq[wid] = q; }
    __syncthreads();
    if (tid == 0) {
        float S = 0.f, Q = 0.f;
        #pragma unroll
        for (int j = 0; j < 8; j++) { S += rs[j]; Q += rq[j]; }
        d_psum[c*8 + part] = S;
        d_psq [c*8 + part] = Q;
    }
}

// ---------------- 2) BN finalize: fold into per-channel affine --------------------
__global__ void k_finalize(const float* __restrict__ gamma, const float* __restrict__ beta) {
    int c = threadIdx.x;
    if (c >= NC) return;
    float s = 0.f, q = 0.f;
    #pragma unroll
    for (int j = 0; j < 8; j++) { s += d_psum[c*8+j]; q += d_psq[c*8+j]; }
    float mean = s * (1.f / NPIX_PER_CH);
    float var  = q * (1.f / NPIX_PER_CH) - mean*mean;
    float inv  = rsqrtf(var + BN_EPS);
    float a = gamma[c] * inv;
    d_ga[c] = a;
    d_gb[c] = beta[c] - mean * a;
}

// ---------------- 3) transform conv weights: Wt[h][cr][ij][o] ---------------------
__global__ void k_wt(const float* __restrict__ cw) {
    int idx = blockIdx.x*256 + threadIdx.x;
    if (idx >= NR*NCR*9*NO) return;
    int o  = idx % NO;  int t = idx / NO;
    int ij = t % 9;     t /= 9;
    int cr = t % NCR;   int h = t / NCR;
    int i = ij / 3, j = ij % 3;
    int c = cr >> 2, r = cr & 3;
    int rs = (r - h) & 3;
    int si, sj;
    switch (h) {
        case 0:  si = i;     sj = j;     break;
        case 1:  si = j;     sj = 2 - i; break;
        case 2:  si = 2 - i; sj = 2 - j; break;
        default: si = 2 - j; sj = i;     break;
    }
    d_wt[idx] = cw[(((o*NC + c)*NR + rs)*3 + si)*3 + sj];
}

// ---------------- 4) transform spatial-attention weights --------------------------
__global__ void k_wsa(const float* __restrict__ sw) {
    int idx = blockIdx.x*256 + threadIdx.x;
    if (idx >= NR*2*NR*49) return;
    int ij = idx % 49; int t = idx / 49;
    int r  = t & 3;    t >>= 2;
    int p  = t & 1;    int h = t >> 1;
    int i = ij / 7, j = ij % 7;
    int rs = (r - h) & 3;
    int si, sj;
    switch (h) {
        case 0:  si = i;     sj = j;     break;
        case 1:  si = j;     sj = 6 - i; break;
        case 2:  si = 6 - i; sj = 6 - j; break;
        default: si = 6 - j; sj = i;     break;
    }
    d_wsa[idx] = sw[(p*NR + rs)*49 + si*7 + sj];
}

// ---------------- 5) spatial squeeze: s_avg / s_max per (b,c,r) -------------------
__global__ void k_pool_scr(const float* __restrict__ x) {
    int id = blockIdx.x;                 // (b*96+c)*4+r  == b*384 + cr
    int c = (id >> 2) % NC;
    int tid = threadIdx.x;
    const float* p = x + (size_t)id * NHW;
    float ga = d_ga[c], gb = d_gb[c];
    float s = 0.f, m = 0.f;
    for (int i = tid; i < NHW; i += 256) {
        float v = fmaxf(fmaf(ga, p[i], gb), 0.f);
        s += v; m = fmaxf(m, v);
    }
    __shared__ float rs[8], rm[8];
    int wid = tid >> 5, lane = tid & 31;
    s = warpSum(s); m = warpMax(m);
    if (lane == 0) { rs[wid] = s; rm[wid] = m; }
    __syncthreads();
    if (tid == 0) {
        float S = 0.f, M = 0.f;
        #pragma unroll
        for (int j = 0; j < 8; j++) { S += rs[j]; M = fmaxf(M, rm[j]); }
        d_savg[id] = S * (1.f / NHW);
        d_smax[id] = M;
    }
}

// ---------------- 6) channel pooling: mean/max over C per (b,r,pixel) -------------
__global__ void k_pool_ch(const float* __restrict__ x) {
    __shared__ float sga[NC], sgb[NC];
    int tid = threadIdx.x;
    if (tid < NC) { sga[tid] = d_ga[tid]; sgb[tid] = d_gb[tid]; }
    __syncthreads();
    int br = blockIdx.y;               // b*4 + r
    int b = br >> 2, r = br & 3;
    int p = blockIdx.x*256 + tid;
    if (p >= NHW) return;
    float s = 0.f, m = 0.f;
    const float* xb = x + (size_t)(b*NCR + r) * NHW + p;
    #pragma unroll 4
    for (int c = 0; c < NC; c++) {
        float v = fmaxf(fmaf(sga[c], xb[(size_t)(c*4) * NHW], sgb[c]), 0.f);
        s += v; m = fmaxf(m, v);
    }
    d_um[br*NHW + p] = s * (1.f / NC);
    d_ux[br*NHW + p] = m;
}

// ---------------- 7) channel attention MLP (tiny) ---------------------------------
__global__ void k_chatt(const float* __restrict__ fc1, const float* __restrict__ fc2) {
    int b = blockIdx.x, tid = threadIdx.x;
    __shared__ float sA[NCR], sM[NCR], f1[2*NCR], f2[NC*8];
    __shared__ float dred[16], hsum[8];
    for (int i = tid; i < NCR; i += 256) { sA[i] = d_savg[b*NCR + i]; sM[i] = d_smax[b*NCR + i]; }
    for (int i = tid; i < 2*NCR; i += 256) { f1[i] = fc1[i]; f2[i] = fc2[i]; }
    __syncthreads();
    int wid = tid >> 5, lane = tid & 31;
    #pragma unroll
    for (int dd = 0; dd < 2; dd++) {
        int d = wid*2 + dd;               // d = ((h*2+e)*2 + sel)
        int sel = d & 1, he = d >> 1;
        int h = he >> 1, e = he & 1;
        const float* sv = sel ? sM : sA;
        float sum = 0.f;
        for (int k = lane; k < NCR; k += 32) {
            int r = k & 3;
            sum += sv[k] * f1[e*NCR + (k & ~3) + (((r - h) & 3))];
        }
        sum = warpSum(sum);
        if (lane == 0) dred[d] = fmaxf(sum, 0.f);   // relu
    }
    __syncthreads();
    if (tid < 8) hsum[tid] = dred[tid*2] + dred[tid*2 + 1];
    __syncthreads();
    for (int idx = tid; idx < NR*NCR; idx += 256) {
        int h = idx / NCR, cr = idx % NCR;
        int c = cr >> 2, r = cr & 3;
        int rs = (r - h) & 3;
        float v = hsum[h*2 + 0] * f2[c*8 + rs]
                + hsum[h*2 + 1] * f2[c*8 + 4 + rs];
        d_ca[b*(NR*NCR) + idx] = sigmoidf(v);
    }
}

// ---------------- 8) spatial attention: 7x7 group conv over pooled maps -----------
__global__ void k_spatt() {
    __shared__ float ws[2*NR*49];
    int tid = threadIdx.x;
    int bh = blockIdx.y;                // b*4 + h
    int b = bh >> 2, h = bh & 3;
    for (int i = tid; i < 2*NR*49; i += 256) ws[i] = d_wsa[h*(2*NR*49) + i];
    __syncthreads();
    int p = blockIdx.x*256 + tid;
    if (p >= NHW) return;
    int y = p / NH, x0 = p % NH;
    float s = 0.f;
    #pragma unroll
    for (int p2 = 0; p2 < 2; p2++) {
        const float* ubase = p2 ? d_ux : d_um;
        #pragma unroll
        for (int r = 0; r < NR; r++) {
            const float* u = ubase + (size_t)(b*4 + r) * NHW;
            const float* w = ws + (p2*4 + r)*49;
            #pragma unroll
            for (int i = 0; i < 7; i++) {
                int Y = y + i - 3;
                if (Y < 0 || Y >= NH) continue;
                #pragma unroll
                for (int j = 0; j < 7; j++) {
                    int X = x0 + j - 3;
                    if (X < 0 || X >= NH) continue;
                    s += u[Y*NH + X] * w[i*7 + j];
                }
            }
        }
    }
    d_sp[bh*NHW + p] = sigmoidf(s);
}

// ---------------- 9) the big gated group conv (O=48, K=384*9, 64x64 out) ----------
// Inner loop uses packed fma.rn.f32x2 (FFMA2) -> 2 fp32 FMAs per fma-pipe slot.
__global__ __launch_bounds__(256, 2) void k_conv(const float* __restrict__ x,
                                                 float* __restrict__ out) {
    int bh = blockIdx.z;                // b*4 + h
    int b = bh >> 2, h = bh & 3;
    int ox0 = blockIdx.x * 32, oy0 = blockIdx.y * 8;
    int tid = threadIdx.x, tx = tid & 31, ty = tid >> 5;

    __shared__ float s_in[8][10][34];
    __shared__ __align__(16) float s_w[8*9*48];
    __shared__ float s_sp[10][34];
    __shared__ float s_ga[NCR], s_gb[NCR];

    for (int i = tid; i < 340; i += 256) {
        int row = i / 34, col = i % 34;
        s_sp[row][col] = d_sp[bh*NHW + (oy0 + row)*NH + ox0 + col];
    }
    for (int i = tid; i < NCR; i += 256) {
        float ca = d_ca[bh*NCR + i];          // sigmoid>0: fold through relu
        int c = i >> 2;
        s_ga[i] = d_ga[c] * ca;
        s_gb[i] = d_gb[c] * ca;
    }

    unsigned long long acc[24];               // 24 x f32x2 = 48 fp32 accumulators
    #pragma unroll
    for (int o = 0; o < 24; o++) acc[o] = 0ull;

    const float* xb = x + (size_t)b * NCR * NHW;

    for (int k = 0; k < 48; k++) {
        int cr0 = k * 8;
        __syncthreads();
        const float4* wsrc = (const float4*)(d_wt + (size_t)(h*NCR + cr0) * 432);
        #pragma unroll 4
        for (int i = tid; i < 864; i += 256) ((float4*)s_w)[i] = wsrc[i];
        #pragma unroll 1
        for (int i = tid; i < 2720; i += 256) {
            int g = i / 340; int rem = i - g*340;
            int row = rem / 34; int col = rem - row*34;
            int cr = cr0 + g;
            float v = xb[(size_t)cr * NHW + (oy0 + row)*NH + ox0 + col];
            v = fmaxf(fmaf(s_ga[cr], v, s_gb[cr]), 0.f) * s_sp[row][col];
            s_in[g][row][col] = v;
        }
        __syncthreads();
        #pragma unroll 1
        for (int g = 0; g < 8; g++) {
            unsigned long long iv2[9];
            #pragma unroll
            for (int ii = 0; ii < 3; ii++)
                #pragma unroll
                for (int jj = 0; jj < 3; jj++) {
                    float v = s_in[g][ty + ii][tx + jj];
                    unsigned int u = __float_as_uint(v);
                    PACK2(iv2[ii*3 + jj], u, u);
                }
            const float* wg = s_w + g*432;
            #pragma unroll
            for (int p = 0; p < 9; p++) {
                #pragma unroll
                for (int o4 = 0; o4 < 12; o4++) {
                    ulonglong2 w2 = *(const ulonglong2*)(wg + p*48 + o4*4);
                    FFMA2(acc[o4*2 + 0], iv2[p], w2.x);
                    FFMA2(acc[o4*2 + 1], iv2[p], w2.y);
                }
            }
        }
    }

    size_t obase = (((size_t)b*144)*4 + h)*4096 + (size_t)(oy0 + ty)*64 + (ox0 + tx);
    #pragma unroll
    for (int o = 0; o < 24; o++) {
        unsigned int lo, hi;
        UNPACK2(lo, hi, acc[o]);
        out[obase + (size_t)(2*o + 0) * 4 * 4096] = __uint_as_float(lo);
        out[obase + (size_t)(2*o + 1) * 4 * 4096] = __uint_as_float(hi);
    }
}

// ---------------- 10) dense concat: crop x into out channels 48..143 --------------
__global__ void k_crop(const float* __restrict__ x, float* __restrict__ out) {
    int idx = blockIdx.x*256 + threadIdx.x;   // over B*C*R*64*16 float4 stores
    if (idx >= NB*NC*NR*64*16) return;
    int q   = idx & 15;
    int y   = (idx >> 4) & 63;
    int brc = idx >> 10;                      // (b*96+c)*4+r
    int b   = brc / NCR;
    int crr = brc % NCR;
    int c   = crr >> 2, r = crr & 3;
    const float* src = x + (size_t)brc * NHW + (size_t)(y + 1)*NH + (q*4 + 1);
    float4 v = make_float4(src[0], src[1], src[2], src[3]);
    size_t off = (((size_t)b*144 + 48 + c)*4 + r)*4096 + (size_t)y*64 + q*4;
    *(float4*)(out + off) = v;
}

// ---------------- launch ----------------------------------------------------------
extern "C" void kernel_launch(void* const* d_in, const int* in_sizes, int n_in,
                              void* d_out, int out_size) {
    const float* x     = (const float*)d_in[0];
    const float* gamma = (const float*)d_in[1];
    const float* beta  = (const float*)d_in[2];
    const float* fc1   = (const float*)d_in[3];
    const float* fc2   = (const float*)d_in[4];
    const float* sa    = (const float*)d_in[5];
    const float* cw    = (const float*)d_in[6];
    float* out = (float*)d_out;
    (void)in_sizes; (void)n_in; (void)out_size;

    k_stats   <<<dim3(NC, 8), 256>>>(x);
    k_finalize<<<1, 128>>>(gamma, beta);
    k_wt      <<<(NR*NCR*9*NO + 255)/256, 256>>>(cw);
    k_wsa     <<<(NR*2*NR*49 + 255)/256, 256>>>(sa);
    k_pool_scr<<<NB*NCR, 256>>>(x);
    k_pool_ch <<<dim3((NHW + 255)/256, NB*NR), 256>>>(x);
    k_chatt   <<<NB, 256>>>(fc1, fc2);
    k_spatt   <<<dim3((NHW + 255)/256, NB*NR), 256>>>();
    k_conv    <<<dim3(2, 8, NB*NR), 256>>>(x, out);
    k_crop    <<<(NB*NC*NR*64*16 + 255)/256, 256>>>(x, out);
}

// round 5
// speedup vs baseline: 1.1333x; 1.1070x over previous
#include <cuda_runtime.h>
#include <math.h>

#define NB 16
#define NC 96
#define NR 4
#define NO 48
#define NH 66
#define NHW (NH*NH)          // 4356
#define NCR (NC*NR)          // 384
#define BN_EPS 2e-5f
#define NPIX_PER_CH (NB*NR*NHW)  // 278784

// ---------------- scratch (device globals) ----------------
__device__ float d_psum[NC*8];
__device__ float d_psq[NC*8];
__device__ float d_ga[NC];
__device__ float d_gb[NC];
__device__ float d_savg[NB*NCR];
__device__ float d_smax[NB*NCR];
__device__ float d_ca[NB*NR*NCR];          // [b][h][cr]
__device__ float d_um[NB*NR*NHW];
__device__ float d_ux[NB*NR*NHW];
__device__ float d_sp[NB*NR*NHW];          // [b*4+h][hw]
__device__ float d_wt[NR*NCR*9*NO];        // [h][cr][ij][o]
__device__ float d_wsa[NR*2*NR*49];

__device__ __forceinline__ float warpSum(float v) {
    #pragma unroll
    for (int o = 16; o; o >>= 1) v += __shfl_down_sync(0xffffffffu, v, o);
    return v;
}
__device__ __forceinline__ float warpMax(float v) {
    #pragma unroll
    for (int o = 16; o; o >>= 1) v = fmaxf(v, __shfl_down_sync(0xffffffffu, v, o));
    return v;
}
__device__ __forceinline__ float sigmoidf(float v) {
    return 1.f / (1.f + expf(-v));
}

// packed f32x2 FMA: d = a*b + d (per-lane fp32, exact)
#define FFMA2(d, a, b) asm("fma.rn.f32x2 %0, %1, %2, %0;" : "+l"(d) : "l"(a), "l"(b))
#define PACK2(d, lo, hi) asm("mov.b64 %0, {%1, %2};" : "=l"(d) : "r"(lo), "r"(hi))
#define UNPACK2(lo, hi, s) asm("mov.b64 {%0, %1}, %2;" : "=r"(lo), "=r"(hi) : "l"(s))

// ---------------- L0: BN statistics ----------------
__global__ void k_stats(const float* __restrict__ x) {
    int c = blockIdx.x, part = blockIdx.y, tid = threadIdx.x;
    float s = 0.f, q = 0.f;
    #pragma unroll
    for (int b2 = 0; b2 < 2; b2++) {
        const float4* p4 = (const float4*)(x + (size_t)((part*2 + b2)*NC + c) * (NR*NHW));
        for (int i = tid; i < NR*NHW/4; i += 256) {
            float4 v = p4[i];
            s += v.x + v.y + v.z + v.w;
            q += v.x*v.x + v.y*v.y + v.z*v.z + v.w*v.w;
        }
    }
    __shared__ float rs[8], rq[8];
    int wid = tid >> 5, lane = tid & 31;
    s = warpSum(s); q = warpSum(q);
    if (lane == 0) { rs[wid] = s; rq[wid] = q; }
    __syncthreads();
    if (tid == 0) {
        float S = 0.f, Q = 0.f;
        #pragma unroll
        for (int j = 0; j < 8; j++) { S += rs[j]; Q += rq[j]; }
        d_psum[c*8 + part] = S;
        d_psq [c*8 + part] = Q;
    }
}

// ---------------- L1: merged finalize + weight transforms ----------------
__global__ void k_prep(const float* __restrict__ gamma, const float* __restrict__ beta,
                       const float* __restrict__ cw, const float* __restrict__ sw) {
    int bx = blockIdx.x, tid = threadIdx.x;
    if (bx == 0) {                       // BN finalize
        if (tid >= NC) return;
        float s = 0.f, q = 0.f;
        #pragma unroll
        for (int j = 0; j < 8; j++) { s += d_psum[tid*8+j]; q += d_psq[tid*8+j]; }
        float mean = s * (1.f / NPIX_PER_CH);
        float var  = q * (1.f / NPIX_PER_CH) - mean*mean;
        float a = gamma[tid] * rsqrtf(var + BN_EPS);
        d_ga[tid] = a;
        d_gb[tid] = beta[tid] - mean * a;
    } else if (bx <= 2592) {             // conv weight transform
        int idx = (bx - 1)*256 + tid;
        if (idx >= NR*NCR*9*NO) return;
        int o  = idx % NO;  int t = idx / NO;
        int ij = t % 9;     t /= 9;
        int cr = t % NCR;   int h = t / NCR;
        int i = ij / 3, j = ij % 3;
        int c = cr >> 2, r = cr & 3;
        int rs = (r - h) & 3;
        int si, sj;
        switch (h) {
            case 0:  si = i;     sj = j;     break;
            case 1:  si = j;     sj = 2 - i; break;
            case 2:  si = 2 - i; sj = 2 - j; break;
            default: si = 2 - j; sj = i;     break;
        }
        d_wt[idx] = cw[(((o*NC + c)*NR + rs)*3 + si)*3 + sj];
    } else {                             // spatial-attention weight transform
        int idx = (bx - 2593)*256 + tid;
        if (idx >= NR*2*NR*49) return;
        int ij = idx % 49; int t = idx / 49;
        int r  = t & 3;    t >>= 2;
        int p  = t & 1;    int h = t >> 1;
        int i = ij / 7, j = ij % 7;
        int rs = (r - h) & 3;
        int si, sj;
        switch (h) {
            case 0:  si = i;     sj = j;     break;
            case 1:  si = j;     sj = 6 - i; break;
            case 2:  si = 6 - i; sj = 6 - j; break;
            default: si = 6 - j; sj = i;     break;
        }
        d_wsa[idx] = sw[(p*NR + rs)*49 + si*7 + sj];
    }
}

// ---------------- L2: merged spatial squeeze + channel pooling ----------------
// channel-pool section needs ceil(4356/256)=18 pixel-blocks per (b,r)!
#define PB 18
__global__ void k_pool(const float* __restrict__ x) {
    int bx = blockIdx.x, tid = threadIdx.x;
    if (bx < NB*NCR) {                   // spatial squeeze per (b,cr)
        int id = bx;
        int c = (id >> 2) % NC;
        const float* p = x + (size_t)id * NHW;
        float ga = d_ga[c], gb = d_gb[c];
        float s = 0.f, m = 0.f;
        for (int i = tid; i < NHW; i += 256) {
            float v = fmaxf(fmaf(ga, p[i], gb), 0.f);
            s += v; m = fmaxf(m, v);
        }
        __shared__ float rs[8], rm[8];
        int wid = tid >> 5, lane = tid & 31;
        s = warpSum(s); m = warpMax(m);
        if (lane == 0) { rs[wid] = s; rm[wid] = m; }
        __syncthreads();
        if (tid == 0) {
            float S = 0.f, M = 0.f;
            #pragma unroll
            for (int j = 0; j < 8; j++) { S += rs[j]; M = fmaxf(M, rm[j]); }
            d_savg[id] = S * (1.f / NHW);
            d_smax[id] = M;
        }
    } else {                             // channel pooling per (b,r,pixel-block)
        __shared__ float sga[NC], sgb[NC];
        if (tid < NC) { sga[tid] = d_ga[tid]; sgb[tid] = d_gb[tid]; }
        __syncthreads();
        int idx = bx - NB*NCR;           // 0 .. PB*64-1
        int pb = idx % PB, br = idx / PB;
        int b = br >> 2, r = br & 3;
        int p = pb*256 + tid;
        if (p >= NHW) return;
        float s = 0.f, m = 0.f;
        const float* xb = x + (size_t)(b*NCR + r) * NHW + p;
        #pragma unroll 4
        for (int c = 0; c < NC; c++) {
            float v = fmaxf(fmaf(sga[c], xb[(size_t)(c*4) * NHW], sgb[c]), 0.f);
            s += v; m = fmaxf(m, v);
        }
        d_um[br*NHW + p] = s * (1.f / NC);
        d_ux[br*NHW + p] = m;
    }
}

// ---------------- L3: channel attention MLP ----------------
__global__ void k_chatt(const float* __restrict__ fc1, const float* __restrict__ fc2) {
    int b = blockIdx.x, tid = threadIdx.x;
    __shared__ float sA[NCR], sM[NCR], f1[2*NCR], f2[NC*8];
    __shared__ float dred[16], hsum[8];
    for (int i = tid; i < NCR; i += 256) { sA[i] = d_savg[b*NCR + i]; sM[i] = d_smax[b*NCR + i]; }
    for (int i = tid; i < 2*NCR; i += 256) { f1[i] = fc1[i]; f2[i] = fc2[i]; }
    __syncthreads();
    int wid = tid >> 5, lane = tid & 31;
    #pragma unroll
    for (int dd = 0; dd < 2; dd++) {
        int d = wid*2 + dd;
        int sel = d & 1, he = d >> 1;
        int h = he >> 1, e = he & 1;
        const float* sv = sel ? sM : sA;
        float sum = 0.f;
        for (int k = lane; k < NCR; k += 32) {
            int r = k & 3;
            sum += sv[k] * f1[e*NCR + (k & ~3) + (((r - h) & 3))];
        }
        sum = warpSum(sum);
        if (lane == 0) dred[d] = fmaxf(sum, 0.f);
    }
    __syncthreads();
    if (tid < 8) hsum[tid] = dred[tid*2] + dred[tid*2 + 1];
    __syncthreads();
    for (int idx = tid; idx < NR*NCR; idx += 256) {
        int h = idx / NCR, cr = idx % NCR;
        int c = cr >> 2, r = cr & 3;
        int rs = (r - h) & 3;
        float v = hsum[h*2 + 0] * f2[c*8 + rs]
                + hsum[h*2 + 1] * f2[c*8 + 4 + rs];
        d_ca[b*(NR*NCR) + idx] = sigmoidf(v);
    }
}

// ---------------- L4: spatial attention 7x7 group conv ----------------
__global__ void k_spatt() {
    __shared__ float ws[2*NR*49];
    int tid = threadIdx.x;
    int bh = blockIdx.y;
    int b = bh >> 2, h = bh & 3;
    for (int i = tid; i < 2*NR*49; i += 256) ws[i] = d_wsa[h*(2*NR*49) + i];
    __syncthreads();
    int p = blockIdx.x*256 + tid;
    if (p >= NHW) return;
    int y = p / NH, x0 = p % NH;
    float s = 0.f;
    #pragma unroll
    for (int p2 = 0; p2 < 2; p2++) {
        const float* ubase = p2 ? d_ux : d_um;
        #pragma unroll
        for (int r = 0; r < NR; r++) {
            const float* u = ubase + (size_t)(b*4 + r) * NHW;
            const float* w = ws + (p2*4 + r)*49;
            #pragma unroll
            for (int i = 0; i < 7; i++) {
                int Y = y + i - 3;
                if (Y < 0 || Y >= NH) continue;
                #pragma unroll
                for (int j = 0; j < 7; j++) {
                    int X = x0 + j - 3;
                    if (X < 0 || X >= NH) continue;
                    s += u[Y*NH + X] * w[i*7 + j];
                }
            }
        }
    }
    d_sp[bh*NHW + p] = sigmoidf(s);
}

// ---------------- L5: the big gated group conv ----------------
// Tiling: block = 64 px wide x 8 rows, 24 of 48 outputs (o-split over grid.x).
// Each thread: 2 adjacent pixels x 24 outputs; weight-pair LDS shared by 2 px.
#define CH 8
__global__ __launch_bounds__(256, 2) void k_conv(const float* __restrict__ x,
                                                 float* __restrict__ out) {
    int o0 = blockIdx.x * 24;            // 0 or 24
    int oy0 = blockIdx.y * 8;
    int bh = blockIdx.z;                 // b*4 + h
    int b = bh >> 2, h = bh & 3;
    int tid = threadIdx.x, tx = tid & 31, ty = tid >> 5;

    __shared__ float s_in[CH][10][68];
    __shared__ __align__(16) float s_w[CH*9*24];
    __shared__ float s_sp[10][68];
    __shared__ float s_ga[NCR], s_gb[NCR];

    for (int i = tid; i < 660; i += 256) {
        int row = i / 66, col = i % 66;
        s_sp[row][col] = d_sp[bh*NHW + (oy0 + row)*NH + col];
    }
    for (int i = tid; i < NCR; i += 256) {
        float ca = d_ca[bh*NCR + i];
        int c = i >> 2;
        s_ga[i] = d_ga[c] * ca;
        s_gb[i] = d_gb[c] * ca;
    }

    unsigned long long acc0[12], acc1[12];   // px0/px1, each 12 o-pairs
    #pragma unroll
    for (int q = 0; q < 12; q++) { acc0[q] = 0ull; acc1[q] = 0ull; }

    const float* xb = x + (size_t)b * NCR * NHW;

    for (int k = 0; k < NCR/CH; k++) {
        int cr0 = k * CH;
        __syncthreads();
        // weights: [g][tap][24] for this o-half
        #pragma unroll 2
        for (int i = tid; i < CH*9*6; i += 256) {
            int g = i / 54; int rem = i - g*54;
            int tap = rem / 6; int q4 = rem - tap*6;
            const float4* src = (const float4*)(d_wt + (size_t)(((h*NCR + cr0 + g)*9 + tap)*48 + o0) + q4*4);
            ((float4*)s_w)[(g*9 + tap)*6 + q4] = *src;
        }
        // gated input: [g][10 rows][66 cols] (68 pad)
        #pragma unroll 1
        for (int i = tid; i < CH*660; i += 256) {
            int g = i / 660; int rem = i - g*660;
            int row = rem / 66; int col = rem - row*66;
            int cr = cr0 + g;
            float v = xb[(size_t)cr * NHW + (oy0 + row)*NH + col];
            v = fmaxf(fmaf(s_ga[cr], v, s_gb[cr]), 0.f) * s_sp[row][col];
            s_in[g][row][col] = v;
        }
        __syncthreads();
        #pragma unroll 1
        for (int g = 0; g < CH; g++) {
            // 4 input scalars per row -> dup-packs
            unsigned long long dup[3][4];
            #pragma unroll
            for (int ii = 0; ii < 3; ii++) {
                const float* rowp = &s_in[g][ty + ii][2*tx];
                #pragma unroll
                for (int jj = 0; jj < 4; jj++) {
                    unsigned int u = __float_as_uint(rowp[jj]);
                    PACK2(dup[ii][jj], u, u);
                }
            }
            const float* wg = s_w + g*216;
            #pragma unroll
            for (int ii = 0; ii < 3; ii++) {
                #pragma unroll
                for (int jj = 0; jj < 3; jj++) {
                    unsigned long long iv0 = dup[ii][jj];
                    unsigned long long iv1 = dup[ii][jj + 1];
                    const float* wt = wg + (ii*3 + jj)*24;
                    #pragma unroll
                    for (int q4 = 0; q4 < 6; q4++) {
                        ulonglong2 w2 = *(const ulonglong2*)(wt + q4*4);
                        FFMA2(acc0[q4*2 + 0], iv0, w2.x);
                        FFMA2(acc0[q4*2 + 1], iv0, w2.y);
                        FFMA2(acc1[q4*2 + 0], iv1, w2.x);
                        FFMA2(acc1[q4*2 + 1], iv1, w2.y);
                    }
                }
            }
        }
    }

    size_t obase = (((size_t)b*144 + o0)*4 + h)*4096 + (size_t)(oy0 + ty)*64 + 2*tx;
    #pragma unroll
    for (int q = 0; q < 12; q++) {
        unsigned int a0, a1, b0, b1;
        UNPACK2(a0, a1, acc0[q]);
        UNPACK2(b0, b1, acc1[q]);
        size_t e = obase + (size_t)(2*q) * 4 * 4096;
        out[e]              = __uint_as_float(a0);   // o=2q,  px0
        out[e + 1]          = __uint_as_float(b0);   // o=2q,  px1
        out[e + 4*4096]     = __uint_as_float(a1);   // o=2q+1,px0
        out[e + 4*4096 + 1] = __uint_as_float(b1);   // o=2q+1,px1
    }
}

// ---------------- L6: dense concat crop ----------------
__global__ void k_crop(const float* __restrict__ x, float* __restrict__ out) {
    int idx = blockIdx.x*256 + threadIdx.x;
    if (idx >= NB*NC*NR*64*16) return;
    int q   = idx & 15;
    int y   = (idx >> 4) & 63;
    int brc = idx >> 10;
    int b   = brc / NCR;
    int crr = brc % NCR;
    int c   = crr >> 2, r = crr & 3;
    const float* src = x + (size_t)brc * NHW + (size_t)(y + 1)*NH + (q*4 + 1);
    float4 v = make_float4(src[0], src[1], src[2], src[3]);
    size_t off = (((size_t)b*144 + 48 + c)*4 + r)*4096 + (size_t)y*64 + q*4;
    *(float4*)(out + off) = v;
}

// ---------------- launch: k_conv is launch index 5 (ncu -s 5 captures it) --------
extern "C" void kernel_launch(void* const* d_in, const int* in_sizes, int n_in,
                              void* d_out, int out_size) {
    const float* x     = (const float*)d_in[0];
    const float* gamma = (const float*)d_in[1];
    const float* beta  = (const float*)d_in[2];
    const float* fc1   = (const float*)d_in[3];
    const float* fc2   = (const float*)d_in[4];
    const float* sa    = (const float*)d_in[5];
    const float* cw    = (const float*)d_in[6];
    float* out = (float*)d_out;
    (void)in_sizes; (void)n_in; (void)out_size;

    k_stats<<<dim3(NC, 8), 256>>>(x);                       // 0
    k_prep <<<2600, 256>>>(gamma, beta, cw, sa);            // 1
    k_pool <<<NB*NCR + PB*NB*NR, 256>>>(x);                 // 2
    k_chatt<<<NB, 256>>>(fc1, fc2);                         // 3
    k_spatt<<<dim3(PB, NB*NR), 256>>>();                    // 4
    k_conv <<<dim3(2, 8, NB*NR), 256>>>(x, out);            // 5  <- profiled
    k_crop <<<(NB*NC*NR*64*16 + 255)/256, 256>>>(x, out);   // 6
}

// round 7
// speedup vs baseline: 1.7233x; 1.5207x over previous
#include <cuda_runtime.h>
#include <cuda_bf16.h>
#include <math.h>
#include <stdint.h>

#define NB 16
#define NC 96
#define NR 4
#define NO 48
#define NH 66
#define NHW (NH*NH)          // 4356
#define NCR (NC*NR)          // 384
#define BN_EPS 2e-5f
#define NPIX_PER_CH (NB*NR*NHW)

// ---- conv GEMM config ----
#define CHC 16                         // channels per chunk
#define NCHUNK 24                      // 384/16
#define WB_PER_CHUNK (9*2*6*32)        // taps x slots(hi/lo) x ntiles x lanes (u64 each) = 3456
#define WB_TOTAL (NR*NCHUNK*WB_PER_CHUNK)

// ---------------- scratch (device globals) ----------------
__device__ float d_psum[NC*8];
__device__ float d_psq[NC*8];
__device__ float d_ga[NC];
__device__ float d_gb[NC];
__device__ float d_savg[NB*NCR];
__device__ float d_smax[NB*NCR];
__device__ float d_ca[NB*NR*NCR];
__device__ float d_um[NB*NR*NHW];
__device__ float d_ux[NB*NR*NHW];
__device__ float d_sp[NB*NR*NHW];
__device__ float d_wsa[NR*2*NR*49];
__device__ unsigned long long d_wb[WB_TOTAL];   // mma-fragment-ordered bf16 weights

__device__ __forceinline__ uint32_t smem_u32(const void* p) {
    uint32_t a;
    asm("{ .reg .u64 t; cvta.to.shared.u64 t, %1; cvt.u32.u64 %0, t; }" : "=r"(a) : "l"(p));
    return a;
}
__device__ __forceinline__ float warpSum(float v) {
    #pragma unroll
    for (int o = 16; o; o >>= 1) v += __shfl_down_sync(0xffffffffu, v, o);
    return v;
}
__device__ __forceinline__ float warpMax(float v) {
    #pragma unroll
    for (int o = 16; o; o >>= 1) v = fmaxf(v, __shfl_down_sync(0xffffffffu, v, o));
    return v;
}
__device__ __forceinline__ float sigmoidf(float v) { return 1.f / (1.f + expf(-v)); }

#define LDSM_X4(r0, r1, r2, r3, addr) \
    asm volatile("ldmatrix.sync.aligned.m8n8.x4.shared.b16 {%0,%1,%2,%3}, [%4];" \
        : "=r"(r0), "=r"(r1), "=r"(r2), "=r"(r3) : "r"(addr))

#define MMA16816(c, a0, a1, a2, a3, b0, b1) \
    asm volatile("mma.sync.aligned.m16n8k16.row.col.f32.bf16.bf16.f32 " \
        "{%0,%1,%2,%3}, {%4,%5,%6,%7}, {%8,%9}, {%0,%1,%2,%3};" \
        : "+f"((c)[0]), "+f"((c)[1]), "+f"((c)[2]), "+f"((c)[3]) \
        : "r"(a0), "r"(a1), "r"(a2), "r"(a3), "r"(b0), "r"(b1))

// ---------------- L0: BN statistics ----------------
__global__ void k_stats(const float* __restrict__ x) {
    int c = blockIdx.x, part = blockIdx.y, tid = threadIdx.x;
    float s = 0.f, q = 0.f;
    #pragma unroll
    for (int b2 = 0; b2 < 2; b2++) {
        const float4* p4 = (const float4*)(x + (size_t)((part*2 + b2)*NC + c) * (NR*NHW));
        for (int i = tid; i < NR*NHW/4; i += 256) {
            float4 v = p4[i];
            s += v.x + v.y + v.z + v.w;
            q += v.x*v.x + v.y*v.y + v.z*v.z + v.w*v.w;
        }
    }
    __shared__ float rs[8], rq[8];
    int wid = tid >> 5, lane = tid & 31;
    s = warpSum(s); q = warpSum(q);
    if (lane == 0) { rs[wid] = s; rq[wid] = q; }
    __syncthreads();
    if (tid == 0) {
        float S = 0.f, Q = 0.f;
        #pragma unroll
        for (int j = 0; j < 8; j++) { S += rs[j]; Q += rq[j]; }
        d_psum[c*8 + part] = S;
        d_psq [c*8 + part] = Q;
    }
}

// ---------------- L1: finalize + SA weights + mma-fragment B prepack ----------------
__global__ void k_prep(const float* __restrict__ gamma, const float* __restrict__ beta,
                       const float* __restrict__ cw, const float* __restrict__ sw) {
    int bx = blockIdx.x, tid = threadIdx.x;
    if (bx == 0) {
        if (tid >= NC) return;
        float s = 0.f, q = 0.f;
        #pragma unroll
        for (int j = 0; j < 8; j++) { s += d_psum[tid*8+j]; q += d_psq[tid*8+j]; }
        float mean = s * (1.f / NPIX_PER_CH);
        float var  = q * (1.f / NPIX_PER_CH) - mean*mean;
        float a = gamma[tid] * rsqrtf(var + BN_EPS);
        d_ga[tid] = a;
        d_gb[tid] = beta[tid] - mean * a;
    } else if (bx <= 7) {                // SA weight transform (1568 elems)
        int idx = (bx - 1)*256 + tid;
        if (idx >= NR*2*NR*49) return;
        int ij = idx % 49; int t = idx / 49;
        int r  = t & 3;    t >>= 2;
        int p  = t & 1;    int h = t >> 1;
        int i = ij / 7, j = ij % 7;
        int rs = (r - h) & 3;
        int si, sj;
        switch (h) {
            case 0:  si = i;     sj = j;     break;
            case 1:  si = j;     sj = 6 - i; break;
            case 2:  si = 6 - i; sj = 6 - j; break;
            default: si = 6 - j; sj = i;     break;
        }
        d_wsa[idx] = sw[(p*NR + rs)*49 + si*7 + sj];
    } else {                             // B prepack into per-lane fragment u64s
        int idx = (bx - 8)*256 + tid;
        if (idx >= WB_TOTAL) return;
        int lane = idx & 31; int t = idx >> 5;
        int nt   = t % 6;    t /= 6;
        int slot = t & 1;    t >>= 1;
        int tap  = t % 9;    t /= 9;
        int chunk = t % NCHUNK;
        int h = t / NCHUNK;
        int n = nt*8 + (lane >> 2);        // output channel o
        int k0 = (lane & 3)*2;
        int i = tap / 3, j = tap % 3, si, sj;
        switch (h) {
            case 0:  si = i;     sj = j;     break;
            case 1:  si = j;     sj = 2 - i; break;
            case 2:  si = 2 - i; sj = 2 - j; break;
            default: si = 2 - j; sj = i;     break;
        }
        unsigned long long pk = 0;
        #pragma unroll
        for (int q = 0; q < 4; q++) {
            int kk = k0 + (q & 1) + (q >> 1)*8;
            int cr = chunk*CHC + kk;
            int c = cr >> 2, r = cr & 3;
            int rs = (r - h) & 3;
            float w = cw[(((n*NC + c)*NR + rs)*3 + si)*3 + sj];
            __nv_bfloat16 hi = __float2bfloat16(w);
            unsigned short bits;
            if (slot == 0) bits = __bfloat16_as_ushort(hi);
            else           bits = __bfloat16_as_ushort(__float2bfloat16(w - __bfloat162float(hi)));
            pk |= (unsigned long long)bits << (q*16);
        }
        d_wb[idx] = pk;
    }
}

// ---------------- L2: spatial squeeze + channel pooling ----------------
#define PB 18
__global__ void k_pool(const float* __restrict__ x) {
    int bx = blockIdx.x, tid = threadIdx.x;
    if (bx < NB*NCR) {
        int id = bx;
        int c = (id >> 2) % NC;
        const float* p = x + (size_t)id * NHW;
        float ga = d_ga[c], gb = d_gb[c];
        float s = 0.f, m = 0.f;
        for (int i = tid; i < NHW; i += 256) {
            float v = fmaxf(fmaf(ga, p[i], gb), 0.f);
            s += v; m = fmaxf(m, v);
        }
        __shared__ float rs[8], rm[8];
        int wid = tid >> 5, lane = tid & 31;
        s = warpSum(s); m = warpMax(m);
        if (lane == 0) { rs[wid] = s; rm[wid] = m; }
        __syncthreads();
        if (tid == 0) {
            float S = 0.f, M = 0.f;
            #pragma unroll
            for (int j = 0; j < 8; j++) { S += rs[j]; M = fmaxf(M, rm[j]); }
            d_savg[id] = S * (1.f / NHW);
            d_smax[id] = M;
        }
    } else {
        __shared__ float sga[NC], sgb[NC];
        if (tid < NC) { sga[tid] = d_ga[tid]; sgb[tid] = d_gb[tid]; }
        __syncthreads();
        int idx = bx - NB*NCR;
        int pb = idx % PB, br = idx / PB;
        int b = br >> 2, r = br & 3;
        int p = pb*256 + tid;
        if (p >= NHW) return;
        float s = 0.f, m = 0.f;
        const float* xb = x + (size_t)(b*NCR + r) * NHW + p;
        #pragma unroll 4
        for (int c = 0; c < NC; c++) {
            float v = fmaxf(fmaf(sga[c], xb[(size_t)(c*4) * NHW], sgb[c]), 0.f);
            s += v; m = fmaxf(m, v);
        }
        d_um[br*NHW + p] = s * (1.f / NC);
        d_ux[br*NHW + p] = m;
    }
}

// ---------------- L3: channel attention MLP ----------------
__global__ void k_chatt(const float* __restrict__ fc1, const float* __restrict__ fc2) {
    int b = blockIdx.x, tid = threadIdx.x;
    __shared__ float sA[NCR], sM[NCR], f1[2*NCR], f2[NC*8];
    __shared__ float dred[16], hsum[8];
    for (int i = tid; i < NCR; i += 256) { sA[i] = d_savg[b*NCR + i]; sM[i] = d_smax[b*NCR + i]; }
    for (int i = tid; i < 2*NCR; i += 256) { f1[i] = fc1[i]; f2[i] = fc2[i]; }
    __syncthreads();
    int wid = tid >> 5, lane = tid & 31;
    #pragma unroll
    for (int dd = 0; dd < 2; dd++) {
        int d = wid*2 + dd;
        int sel = d & 1, he = d >> 1;
        int h = he >> 1, e = he & 1;
        const float* sv = sel ? sM : sA;
        float sum = 0.f;
        for (int k = lane; k < NCR; k += 32) {
            int r = k & 3;
            sum += sv[k] * f1[e*NCR + (k & ~3) + (((r - h) & 3))];
        }
        sum = warpSum(sum);
        if (lane == 0) dred[d] = fmaxf(sum, 0.f);
    }
    __syncthreads();
    if (tid < 8) hsum[tid] = dred[tid*2] + dred[tid*2 + 1];
    __syncthreads();
    for (int idx = tid; idx < NR*NCR; idx += 256) {
        int h = idx / NCR, cr = idx % NCR;
        int c = cr >> 2, r = cr & 3;
        int rs = (r - h) & 3;
        float v = hsum[h*2 + 0] * f2[c*8 + rs]
                + hsum[h*2 + 1] * f2[c*8 + 4 + rs];
        d_ca[b*(NR*NCR) + idx] = sigmoidf(v);
    }
}

// ---------------- L4: spatial attention 7x7 group conv ----------------
__global__ void k_spatt() {
    __shared__ float ws[2*NR*49];
    int tid = threadIdx.x;
    int bh = blockIdx.y;
    int b = bh >> 2, h = bh & 3;
    for (int i = tid; i < 2*NR*49; i += 256) ws[i] = d_wsa[h*(2*NR*49) + i];
    __syncthreads();
    int p = blockIdx.x*256 + tid;
    if (p >= NHW) return;
    int y = p / NH, x0 = p % NH;
    float s = 0.f;
    #pragma unroll
    for (int p2 = 0; p2 < 2; p2++) {
        const float* ubase = p2 ? d_ux : d_um;
        #pragma unroll
        for (int r = 0; r < NR; r++) {
            const float* u = ubase + (size_t)(b*4 + r) * NHW;
            const float* w = ws + (p2*4 + r)*49;
            #pragma unroll
            for (int i = 0; i < 7; i++) {
                int Y = y + i - 3;
                if (Y < 0 || Y >= NH) continue;
                #pragma unroll
                for (int j = 0; j < 7; j++) {
                    int X = x0 + j - 3;
                    if (X < 0 || X >= NH) continue;
                    s += u[Y*NH + X] * w[i*7 + j];
                }
            }
        }
    }
    d_sp[bh*NHW + p] = sigmoidf(s);
}

// ---------------- L5: gated group conv via split-bf16 HMMA (mma.sync) ----------------
// Block: 256 thr = 8 warps; M=128 px (2 output rows x 64), N=48, shift-trick taps.
__global__ __launch_bounds__(256, 2) void k_conv(const float* __restrict__ x,
                                                 float* __restrict__ out) {
    __shared__ __align__(16) unsigned long long sB[WB_PER_CHUNK];   // 27648 B
    __shared__ __align__(16) unsigned short sA[4*66*32];            // 16896 B: [row][col][hi16|lo16]
    __shared__ float s_sp[4*66];
    __shared__ float s_ga[NCR], s_gb[NCR];

    int ytile = blockIdx.x, bh = blockIdx.y;
    int b = bh >> 2, h = bh & 3;
    int y0 = ytile * 2;
    int tid = threadIdx.x, lane = tid & 31, w = tid >> 5;

    for (int i = tid; i < NCR; i += 256) {
        float ca = d_ca[bh*NCR + i];
        int c = i >> 2;
        s_ga[i] = d_ga[c] * ca;
        s_gb[i] = d_gb[c] * ca;
    }
    for (int i = tid; i < 4*66; i += 256) {
        int row = i / 66, col = i - row*66;
        s_sp[i] = d_sp[bh*NHW + (y0 + row)*NH + col];
    }

    float acc[6][4];
    #pragma unroll
    for (int nt = 0; nt < 6; nt++)
        #pragma unroll
        for (int q = 0; q < 4; q++) acc[nt][q] = 0.f;

    // per-lane ldmatrix base address (A fragment geometry)
    int matrix = lane >> 3, mrow = lane & 7;
    int fragrow = ((matrix & 1) << 3) + mrow;   // pixel index within warp's m16 tile
    int colhalf = matrix >> 1;                  // k cols 0-7 vs 8-15
    int px_x = (w & 3)*16 + fragrow;            // input col base (before +dj)
    int px_y = (w >> 2);                        // input row base within sA (before +di)
    uint32_t lane_addr0 = smem_u32(sA) + (uint32_t)((px_y*66 + px_x)*64 + colhalf*16);

    const float* xb = x + (size_t)b * NCR * NHW;

    for (int chunk = 0; chunk < NCHUNK; chunk++) {
        __syncthreads();
        // stage B chunk (27648 B)
        {
            const uint4* src = (const uint4*)(d_wb + (size_t)(h*NCHUNK + chunk)*WB_PER_CHUNK);
            uint4* dst = (uint4*)sB;
            #pragma unroll
            for (int i = tid; i < WB_PER_CHUNK/2; i += 256) dst[i] = src[i];
        }
        // build gated split-bf16 A tile: 16 ch x 4 rows x 66 cols
        int cr0 = chunk * CHC;
        for (int i = tid; i < CHC*264; i += 256) {
            int ch = i / 264; int rem = i - ch*264;
            int row = rem / 66, col = rem - row*66;
            int cr = cr0 + ch;
            float v = xb[(size_t)cr * NHW + (y0 + row)*NH + col];
            v = fmaxf(fmaf(s_ga[cr], v, s_gb[cr]), 0.f) * s_sp[row*66 + col];
            __nv_bfloat16 hi = __float2bfloat16(v);
            float rm = v - __bfloat162float(hi);
            __nv_bfloat16 lo = __float2bfloat16(rm);
            int base = (row*66 + col)*32;
            sA[base + ch]      = __bfloat16_as_ushort(hi);
            sA[base + 16 + ch] = __bfloat16_as_ushort(lo);
        }
        __syncthreads();
        #pragma unroll
        for (int tap = 0; tap < 9; tap++) {
            const int di = tap / 3, dj = tap % 3;
            uint32_t addr = lane_addr0 + (uint32_t)((di*66 + dj)*64);
            uint32_t h0, h1, h2, h3, l0, l1, l2, l3;
            LDSM_X4(h0, h1, h2, h3, addr);        // hi fragment
            LDSM_X4(l0, l1, l2, l3, addr + 32);   // lo fragment
            const unsigned long long* bp = sB + tap*384;   // [slot][nt][lane]
            #pragma unroll
            for (int nt = 0; nt < 6; nt++) {
                unsigned long long bh2 = bp[nt*32 + lane];
                unsigned long long bl2 = bp[192 + nt*32 + lane];
                uint32_t bh0 = (uint32_t)bh2, bh1 = (uint32_t)(bh2 >> 32);
                uint32_t bl0 = (uint32_t)bl2, bl1 = (uint32_t)(bl2 >> 32);
                MMA16816(acc[nt], h0, h1, h2, h3, bh0, bh1);   // hi*hi
                MMA16816(acc[nt], l0, l1, l2, l3, bh0, bh1);   // lo*hi
                MMA16816(acc[nt], h0, h1, h2, h3, bl0, bl1);   // hi*lo
            }
        }
    }

    // epilogue: C fragment -> out[b, o, h, y, x]
    int ox = (w & 3)*16 + (lane >> 2);
    int oy = y0 + (w >> 2);
    #pragma unroll
    for (int nt = 0; nt < 6; nt++) {
        int o0 = nt*8 + (lane & 3)*2;
        size_t i0 = (((size_t)(b*144 + o0))*4 + h)*4096 + (size_t)oy*64;
        out[i0 + ox]               = acc[nt][0];   // (o0,   px)
        out[i0 + 16384 + ox]       = acc[nt][1];   // (o0+1, px)
        out[i0 + ox + 8]           = acc[nt][2];   // (o0,   px+8)
        out[i0 + 16384 + ox + 8]   = acc[nt][3];   // (o0+1, px+8)
    }
}

// ---------------- L6: dense concat crop ----------------
__global__ void k_crop(const float* __restrict__ x, float* __restrict__ out) {
    int idx = blockIdx.x*256 + threadIdx.x;
    if (idx >= NB*NC*NR*64*16) return;
    int q   = idx & 15;
    int y   = (idx >> 4) & 63;
    int brc = idx >> 10;
    int b   = brc / NCR;
    int crr = brc % NCR;
    int c   = crr >> 2, r = crr & 3;
    const float* src = x + (size_t)brc * NHW + (size_t)(y + 1)*NH + (q*4 + 1);
    float4 v = make_float4(src[0], src[1], src[2], src[3]);
    size_t off = (((size_t)b*144 + 48 + c)*4 + r)*4096 + (size_t)y*64 + q*4;
    *(float4*)(out + off) = v;
}

// ---------------- launch ----------------
extern "C" void kernel_launch(void* const* d_in, const int* in_sizes, int n_in,
                              void* d_out, int out_size) {
    const float* x     = (const float*)d_in[0];
    const float* gamma = (const float*)d_in[1];
    const float* beta  = (const float*)d_in[2];
    const float* fc1   = (const float*)d_in[3];
    const float* fc2   = (const float*)d_in[4];
    const float* sa    = (const float*)d_in[5];
    const float* cw    = (const float*)d_in[6];
    float* out = (float*)d_out;
    (void)in_sizes; (void)n_in; (void)out_size;

    int prep_blocks = 8 + (WB_TOTAL + 255)/256;                // 8 + 1296
    k_stats<<<dim3(NC, 8), 256>>>(x);                          // 0
    k_prep <<<prep_blocks, 256>>>(gamma, beta, cw, sa);        // 1
    k_pool <<<NB*NCR + PB*NB*NR, 256>>>(x);                    // 2
    k_chatt<<<NB, 256>>>(fc1, fc2);                            // 3
    k_spatt<<<dim3(PB, NB*NR), 256>>>();                       // 4
    k_conv <<<dim3(32, NB*NR), 256>>>(x, out);                 // 5  <- profiled
    k_crop <<<(NB*NC*NR*64*16 + 255)/256, 256>>>(x, out);      // 6
}

// round 8
// speedup vs baseline: 2.0061x; 1.1641x over previous
#include <cuda_runtime.h>
#include <cuda_fp16.h>
#include <math.h>
#include <stdint.h>

#define NB 16
#define NC 96
#define NR 4
#define NO 48
#define NH 66
#define NHW (NH*NH)          // 4356
#define NCR (NC*NR)          // 384
#define BN_EPS 2e-5f
#define NPIX_PER_CH (NB*NR*NHW)

// ---- conv GEMM config ----
#define CHC 16                          // channels per chunk
#define NCHUNK 24                       // 384/16
#define WB_PER_CHUNK (9*6*32)           // taps x ntiles x lanes (u64 each) = 1728
#define WB_TOTAL (NR*NCHUNK*WB_PER_CHUNK)   // 165888

// ---------------- scratch (device globals) ----------------
__device__ float d_psum[NC*8];
__device__ float d_psq[NC*8];
__device__ float d_savg[NB*NCR];
__device__ float d_smax[NB*NCR];
__device__ float d_ca[NB*NR*NCR];
__device__ float d_um[NB*NR*NHW];
__device__ float d_ux[NB*NR*NHW];
__device__ float d_sp[NB*NR*NHW];
__device__ float d_wsa[NR*2*NR*49];
__device__ unsigned long long d_wb[WB_TOTAL];   // mma-fragment-ordered fp16 weights

__device__ __forceinline__ uint32_t smem_u32(const void* p) {
    uint32_t a;
    asm("{ .reg .u64 t; cvta.to.shared.u64 t, %1; cvt.u32.u64 %0, t; }" : "=r"(a) : "l"(p));
    return a;
}
__device__ __forceinline__ float warpSum(float v) {
    #pragma unroll
    for (int o = 16; o; o >>= 1) v += __shfl_down_sync(0xffffffffu, v, o);
    return v;
}
__device__ __forceinline__ float warpMax(float v) {
    #pragma unroll
    for (int o = 16; o; o >>= 1) v = fmaxf(v, __shfl_down_sync(0xffffffffu, v, o));
    return v;
}
__device__ __forceinline__ float sigmoidf(float v) { return 1.f / (1.f + expf(-v)); }

#define LDSM_X4(r0, r1, r2, r3, addr) \
    asm volatile("ldmatrix.sync.aligned.m8n8.x4.shared.b16 {%0,%1,%2,%3}, [%4];" \
        : "=r"(r0), "=r"(r1), "=r"(r2), "=r"(r3) : "r"(addr))

#define MMA16816F16(c, a0, a1, a2, a3, b0, b1) \
    asm volatile("mma.sync.aligned.m16n8k16.row.col.f32.f16.f16.f32 " \
        "{%0,%1,%2,%3}, {%4,%5,%6,%7}, {%8,%9}, {%0,%1,%2,%3};" \
        : "+f"((c)[0]), "+f"((c)[1]), "+f"((c)[2]), "+f"((c)[3]) \
        : "r"(a0), "r"(a1), "r"(a2), "r"(a3), "r"(b0), "r"(b1))

// compute BN affine for channel c from partial sums
__device__ __forceinline__ void bn_affine(int c, const float* gamma, const float* beta,
                                          float& ga, float& gb) {
    float s = 0.f, q = 0.f;
    #pragma unroll
    for (int j = 0; j < 8; j++) { s += d_psum[c*8+j]; q += d_psq[c*8+j]; }
    float mean = s * (1.f / NPIX_PER_CH);
    float var  = q * (1.f / NPIX_PER_CH) - mean*mean;
    ga = gamma[c] * rsqrtf(var + BN_EPS);
    gb = beta[c] - mean * ga;
}

// ---------------- L0: stats + SA weights + fp16 B prepack (independent parts) -----
__global__ void k_init(const float* __restrict__ x, const float* __restrict__ cw,
                       const float* __restrict__ sw) {
    int bx = blockIdx.x, tid = threadIdx.x;
    if (bx < 768) {                      // BN statistics
        int c = bx >> 3, part = bx & 7;
        float s = 0.f, q = 0.f;
        #pragma unroll
        for (int b2 = 0; b2 < 2; b2++) {
            const float4* p4 = (const float4*)(x + (size_t)((part*2 + b2)*NC + c) * (NR*NHW));
            for (int i = tid; i < NR*NHW/4; i += 256) {
                float4 v = p4[i];
                s += v.x + v.y + v.z + v.w;
                q += v.x*v.x + v.y*v.y + v.z*v.z + v.w*v.w;
            }
        }
        __shared__ float rs[8], rq[8];
        int wid = tid >> 5, lane = tid & 31;
        s = warpSum(s); q = warpSum(q);
        if (lane == 0) { rs[wid] = s; rq[wid] = q; }
        __syncthreads();
        if (tid == 0) {
            float S = 0.f, Q = 0.f;
            #pragma unroll
            for (int j = 0; j < 8; j++) { S += rs[j]; Q += rq[j]; }
            d_psum[c*8 + part] = S;
            d_psq [c*8 + part] = Q;
        }
    } else if (bx < 775) {               // SA weight transform (1568 elems)
        int idx = (bx - 768)*256 + tid;
        if (idx >= NR*2*NR*49) return;
        int ij = idx % 49; int t = idx / 49;
        int r  = t & 3;    t >>= 2;
        int p  = t & 1;    int h = t >> 1;
        int i = ij / 7, j = ij % 7;
        int rs = (r - h) & 3;
        int si, sj;
        switch (h) {
            case 0:  si = i;     sj = j;     break;
            case 1:  si = j;     sj = 6 - i; break;
            case 2:  si = 6 - i; sj = 6 - j; break;
            default: si = 6 - j; sj = i;     break;
        }
        d_wsa[idx] = sw[(p*NR + rs)*49 + si*7 + sj];
    } else {                             // fp16 B prepack into per-lane fragment u64s
        int idx = (bx - 775)*256 + tid;
        if (idx >= WB_TOTAL) return;
        int lane = idx & 31; int t = idx >> 5;
        int nt   = t % 6;    t /= 6;
        int tap  = t % 9;    t /= 9;
        int chunk = t % NCHUNK;
        int h = t / NCHUNK;
        int n = nt*8 + (lane >> 2);
        int k0 = (lane & 3)*2;
        int i = tap / 3, j = tap % 3, si, sj;
        switch (h) {
            case 0:  si = i;     sj = j;     break;
            case 1:  si = j;     sj = 2 - i; break;
            case 2:  si = 2 - i; sj = 2 - j; break;
            default: si = 2 - j; sj = i;     break;
        }
        unsigned long long pk = 0;
        #pragma unroll
        for (int q = 0; q < 4; q++) {
            int kk = k0 + (q & 1) + (q >> 1)*8;
            int cr = chunk*CHC + kk;
            int c = cr >> 2, r = cr & 3;
            int rs = (r - h) & 3;
            float w = cw[(((n*NC + c)*NR + rs)*3 + si)*3 + sj];
            unsigned short bits = __half_as_ushort(__float2half(w));
            pk |= (unsigned long long)bits << (q*16);
        }
        d_wb[idx] = pk;
    }
}

// ---------------- L1: spatial squeeze + channel pooling (inline BN affine) --------
#define PB 18
__global__ void k_pool(const float* __restrict__ x, const float* __restrict__ gamma,
                       const float* __restrict__ beta) {
    int bx = blockIdx.x, tid = threadIdx.x;
    if (bx < NB*NCR) {
        int id = bx;
        int c = (id >> 2) % NC;
        float ga, gb;
        bn_affine(c, gamma, beta, ga, gb);
        const float* p = x + (size_t)id * NHW;
        float s = 0.f, m = 0.f;
        for (int i = tid; i < NHW; i += 256) {
            float v = fmaxf(fmaf(ga, p[i], gb), 0.f);
            s += v; m = fmaxf(m, v);
        }
        __shared__ float rs[8], rm[8];
        int wid = tid >> 5, lane = tid & 31;
        s = warpSum(s); m = warpMax(m);
        if (lane == 0) { rs[wid] = s; rm[wid] = m; }
        __syncthreads();
        if (tid == 0) {
            float S = 0.f, M = 0.f;
            #pragma unroll
            for (int j = 0; j < 8; j++) { S += rs[j]; M = fmaxf(M, rm[j]); }
            d_savg[id] = S * (1.f / NHW);
            d_smax[id] = M;
        }
    } else {
        __shared__ float sga[NC], sgb[NC];
        if (tid < NC) bn_affine(tid, gamma, beta, sga[tid], sgb[tid]);
        __syncthreads();
        int idx = bx - NB*NCR;
        int pb = idx % PB, br = idx / PB;
        int b = br >> 2, r = br & 3;
        int p = pb*256 + tid;
        if (p >= NHW) return;
        float s = 0.f, m = 0.f;
        const float* xb = x + (size_t)(b*NCR + r) * NHW + p;
        #pragma unroll 4
        for (int c = 0; c < NC; c++) {
            float v = fmaxf(fmaf(sga[c], xb[(size_t)(c*4) * NHW], sgb[c]), 0.f);
            s += v; m = fmaxf(m, v);
        }
        d_um[br*NHW + p] = s * (1.f / NC);
        d_ux[br*NHW + p] = m;
    }
}

// ---------------- L2: merged channel-attention MLP + spatial attention ------------
__global__ void k_att(const float* __restrict__ fc1, const float* __restrict__ fc2) {
    int bx = blockIdx.x, tid = threadIdx.x;
    if (bx < NB) {                       // channel attention for batch b
        int b = bx;
        __shared__ float sA[NCR], sM[NCR], f1[2*NCR], f2[NC*8];
        __shared__ float dred[16], hsum[8];
        for (int i = tid; i < NCR; i += 256) { sA[i] = d_savg[b*NCR + i]; sM[i] = d_smax[b*NCR + i]; }
        for (int i = tid; i < 2*NCR; i += 256) { f1[i] = fc1[i]; f2[i] = fc2[i]; }
        __syncthreads();
        int wid = tid >> 5, lane = tid & 31;
        #pragma unroll
        for (int dd = 0; dd < 2; dd++) {
            int d = wid*2 + dd;
            int sel = d & 1, he = d >> 1;
            int h = he >> 1, e = he & 1;
            const float* sv = sel ? sM : sA;
            float sum = 0.f;
            for (int k = lane; k < NCR; k += 32) {
                int r = k & 3;
                sum += sv[k] * f1[e*NCR + (k & ~3) + (((r - h) & 3))];
            }
            sum = warpSum(sum);
            if (lane == 0) dred[d] = fmaxf(sum, 0.f);
        }
        __syncthreads();
        if (tid < 8) hsum[tid] = dred[tid*2] + dred[tid*2 + 1];
        __syncthreads();
        for (int idx = tid; idx < NR*NCR; idx += 256) {
            int h = idx / NCR, cr = idx % NCR;
            int c = cr >> 2, r = cr & 3;
            int rs = (r - h) & 3;
            float v = hsum[h*2 + 0] * f2[c*8 + rs]
                    + hsum[h*2 + 1] * f2[c*8 + 4 + rs];
            d_ca[b*(NR*NCR) + idx] = sigmoidf(v);
        }
    } else {                             // spatial attention 7x7
        __shared__ float ws[2*NR*49];
        int idx = bx - NB;
        int pb = idx % PB, bh = idx / PB;
        int b = bh >> 2, h = bh & 3;
        for (int i = tid; i < 2*NR*49; i += 256) ws[i] = d_wsa[h*(2*NR*49) + i];
        __syncthreads();
        int p = pb*256 + tid;
        if (p >= NHW) return;
        int y = p / NH, x0 = p % NH;
        float s = 0.f;
        #pragma unroll
        for (int p2 = 0; p2 < 2; p2++) {
            const float* ubase = p2 ? d_ux : d_um;
            #pragma unroll
            for (int r = 0; r < NR; r++) {
                const float* u = ubase + (size_t)(b*4 + r) * NHW;
                const float* w = ws + (p2*4 + r)*49;
                #pragma unroll
                for (int i = 0; i < 7; i++) {
                    int Y = y + i - 3;
                    if (Y < 0 || Y >= NH) continue;
                    #pragma unroll
                    for (int j = 0; j < 7; j++) {
                        int X = x0 + j - 3;
                        if (X < 0 || X >= NH) continue;
                        s += u[Y*NH + X] * w[i*7 + j];
                    }
                }
            }
        }
        d_sp[bh*NHW + p] = sigmoidf(s);
    }
}

// ---------------- L3 (PROFILED): gated group conv via 2-term fp16 HMMA ------------
// Block: 256 thr = 8 warps; M=128 px (2 output rows x 64), N=48, shift-trick taps.
__global__ __launch_bounds__(256, 3) void k_conv(const float* __restrict__ x,
                                                 const float* __restrict__ gamma,
                                                 const float* __restrict__ beta,
                                                 float* __restrict__ out) {
    __shared__ __align__(16) unsigned long long sB[WB_PER_CHUNK];   // 13824 B
    __shared__ __align__(16) unsigned short sA[4*66*32];            // 16896 B: [row][col][16hi|16lo]
    __shared__ float s_sp[4*66];
    __shared__ float s_ga[NCR], s_gb[NCR];
    __shared__ float s_gac[NC], s_gbc[NC];

    int ytile = blockIdx.x, bh = blockIdx.y;
    int b = bh >> 2, h = bh & 3;
    int y0 = ytile * 2;
    int tid = threadIdx.x, lane = tid & 31, w = tid >> 5;

    if (tid < NC) bn_affine(tid, gamma, beta, s_gac[tid], s_gbc[tid]);
    for (int i = tid; i < 4*66; i += 256) {
        int row = i / 66, col = i - row*66;
        s_sp[i] = d_sp[bh*NHW + (y0 + row)*NH + col];
    }
    __syncthreads();
    for (int i = tid; i < NCR; i += 256) {
        float ca = d_ca[bh*NCR + i];
        int c = i >> 2;
        s_ga[i] = s_gac[c] * ca;
        s_gb[i] = s_gbc[c] * ca;
    }

    float acc[6][4];
    #pragma unroll
    for (int nt = 0; nt < 6; nt++)
        #pragma unroll
        for (int q = 0; q < 4; q++) acc[nt][q] = 0.f;

    // per-lane ldmatrix base address (A fragment geometry, verified round 7)
    int matrix = lane >> 3, mrow = lane & 7;
    int fragrow = ((matrix & 1) << 3) + mrow;
    int colhalf = matrix >> 1;
    int px_x = (w & 3)*16 + fragrow;
    int px_y = (w >> 2);
    uint32_t lane_addr0 = smem_u32(sA) + (uint32_t)((px_y*66 + px_x)*64 + colhalf*16);

    const float* xb = x + (size_t)b * NCR * NHW;

    for (int chunk = 0; chunk < NCHUNK; chunk++) {
        __syncthreads();
        // stage B chunk (13824 B)
        {
            const uint4* src = (const uint4*)(d_wb + (size_t)(h*NCHUNK + chunk)*WB_PER_CHUNK);
            uint4* dst = (uint4*)sB;
            #pragma unroll
            for (int i = tid; i < WB_PER_CHUNK/2; i += 256) dst[i] = src[i];
        }
        // gated split-fp16 A tile: 16 ch x 4 rows x 66 cols
        int cr0 = chunk * CHC;
        for (int i = tid; i < CHC*264; i += 256) {
            int ch = i / 264; int rem = i - ch*264;
            int row = rem / 66, col = rem - row*66;
            int cr = cr0 + ch;
            float v = xb[(size_t)cr * NHW + (y0 + row)*NH + col];
            v = fmaxf(fmaf(s_ga[cr], v, s_gb[cr]), 0.f) * s_sp[row*66 + col];
            __half hi = __float2half(v);
            __half lo = __float2half(v - __half2float(hi));
            int base = (row*66 + col)*32;
            sA[base + ch]      = __half_as_ushort(hi);
            sA[base + 16 + ch] = __half_as_ushort(lo);
        }
        __syncthreads();
        #pragma unroll
        for (int tap = 0; tap < 9; tap++) {
            const int di = tap / 3, dj = tap % 3;
            uint32_t addr = lane_addr0 + (uint32_t)((di*66 + dj)*64);
            uint32_t h0, h1, h2, h3, l0, l1, l2, l3;
            LDSM_X4(h0, h1, h2, h3, addr);        // hi fragment
            LDSM_X4(l0, l1, l2, l3, addr + 32);   // lo fragment
            const unsigned long long* bp = sB + tap*192;
            #pragma unroll
            for (int nt = 0; nt < 6; nt++) {
                unsigned long long b2 = bp[nt*32 + lane];
                uint32_t b0 = (uint32_t)b2, b1 = (uint32_t)(b2 >> 32);
                MMA16816F16(acc[nt], h0, h1, h2, h3, b0, b1);   // hi * w
                MMA16816F16(acc[nt], l0, l1, l2, l3, b0, b1);   // lo * w
            }
        }
    }

    // epilogue: C fragment -> out[b, o, h, y, x]
    int ox = (w & 3)*16 + (lane >> 2);
    int oy = y0 + (w >> 2);
    #pragma unroll
    for (int nt = 0; nt < 6; nt++) {
        int o0 = nt*8 + (lane & 3)*2;
        size_t i0 = (((size_t)(b*144 + o0))*4 + h)*4096 + (size_t)oy*64;
        out[i0 + ox]               = acc[nt][0];
        out[i0 + 16384 + ox]       = acc[nt][1];
        out[i0 + ox + 8]           = acc[nt][2];
        out[i0 + 16384 + ox + 8]   = acc[nt][3];
    }
}

// ---------------- L4: dense concat crop ----------------
__global__ void k_crop(const float* __restrict__ x, float* __restrict__ out) {
    int idx = blockIdx.x*256 + threadIdx.x;
    if (idx >= NB*NC*NR*64*16) return;
    int q   = idx & 15;
    int y   = (idx >> 4) & 63;
    int brc = idx >> 10;
    int b   = brc / NCR;
    int crr = brc % NCR;
    int c   = crr >> 2, r = crr & 3;
    const float* src = x + (size_t)brc * NHW + (size_t)(y + 1)*NH + (q*4 + 1);
    float4 v = make_float4(src[0], src[1], src[2], src[3]);
    size_t off = (((size_t)b*144 + 48 + c)*4 + r)*4096 + (size_t)y*64 + q*4;
    *(float4*)(out + off) = v;
}

// ---------------- launch: k_conv is launch index 3 (the ncu-captured one) ---------
extern "C" void kernel_launch(void* const* d_in, const int* in_sizes, int n_in,
                              void* d_out, int out_size) {
    const float* x     = (const float*)d_in[0];
    const float* gamma = (const float*)d_in[1];
    const float* beta  = (const float*)d_in[2];
    const float* fc1   = (const float*)d_in[3];
    const float* fc2   = (const float*)d_in[4];
    const float* sa    = (const float*)d_in[5];
    const float* cw    = (const float*)d_in[6];
    float* out = (float*)d_out;
    (void)in_sizes; (void)n_in; (void)out_size;

    int init_blocks = 775 + (WB_TOTAL + 255)/256;              // 775 + 648
    k_init<<<init_blocks, 256>>>(x, cw, sa);                   // 0
    k_pool<<<NB*NCR + PB*NB*NR, 256>>>(x, gamma, beta);        // 1
    k_att <<<NB + PB*NB*NR, 256>>>(fc1, fc2);                  // 2
    k_conv<<<dim3(32, NB*NR), 256>>>(x, gamma, beta, out);     // 3  <- profiled
    k_crop<<<(NB*NC*NR*64*16 + 255)/256, 256>>>(x, out);       // 4
}

// round 9
// speedup vs baseline: 2.2599x; 1.1265x over previous
#include <cuda_runtime.h>
#include <cuda_fp16.h>
#include <math.h>
#include <stdint.h>

#define NB 16
#define NC 96
#define NR 4
#define NO 48
#define NH 66
#define NHW (NH*NH)          // 4356
#define NCR (NC*NR)          // 384
#define BN_EPS 2e-5f
#define NPIX_PER_CH (NB*NR*NHW)

// ---- conv GEMM config ----
#define CHC 16                          // channels per chunk
#define NCHUNK 24                       // 384/16
#define WB_PER_CHUNK (9*6*32)           // taps x ntiles x lanes (u64 each) = 1728
#define WB_TOTAL (NR*NCHUNK*WB_PER_CHUNK)   // 165888

// ---------------- scratch (device globals) ----------------
__device__ float d_psum[NC*8];
__device__ float d_psq[NC*8];
__device__ float d_savg[NB*NCR];
__device__ float d_smax[NB*NCR];
__device__ float d_ca[NB*NR*NCR];
__device__ float d_um[NB*NR*NHW];
__device__ float d_ux[NB*NR*NHW];
__device__ float d_sp[NB*NR*NHW];
__device__ float d_wsa[NR*2*NR*49];
__device__ unsigned long long d_wb[WB_TOTAL];   // mma-fragment-ordered fp16 weights

__device__ __forceinline__ uint32_t smem_u32(const void* p) {
    uint32_t a;
    asm("{ .reg .u64 t; cvta.to.shared.u64 t, %1; cvt.u32.u64 %0, t; }" : "=r"(a) : "l"(p));
    return a;
}
__device__ __forceinline__ float warpSum(float v) {
    #pragma unroll
    for (int o = 16; o; o >>= 1) v += __shfl_down_sync(0xffffffffu, v, o);
    return v;
}
__device__ __forceinline__ float warpMax(float v) {
    #pragma unroll
    for (int o = 16; o; o >>= 1) v = fmaxf(v, __shfl_down_sync(0xffffffffu, v, o));
    return v;
}
__device__ __forceinline__ float sigmoidf(float v) { return 1.f / (1.f + expf(-v)); }

#define LDSM_X4(r0, r1, r2, r3, addr) \
    asm volatile("ldmatrix.sync.aligned.m8n8.x4.shared.b16 {%0,%1,%2,%3}, [%4];" \
        : "=r"(r0), "=r"(r1), "=r"(r2), "=r"(r3) : "r"(addr))

#define MMA16816F16(c, a0, a1, a2, a3, b0, b1) \
    asm volatile("mma.sync.aligned.m16n8k16.row.col.f32.f16.f16.f32 " \
        "{%0,%1,%2,%3}, {%4,%5,%6,%7}, {%8,%9}, {%0,%1,%2,%3};" \
        : "+f"((c)[0]), "+f"((c)[1]), "+f"((c)[2]), "+f"((c)[3]) \
        : "r"(a0), "r"(a1), "r"(a2), "r"(a3), "r"(b0), "r"(b1))

// compute BN affine for channel c from partial sums
__device__ __forceinline__ void bn_affine(int c, const float* gamma, const float* beta,
                                          float& ga, float& gb) {
    float s = 0.f, q = 0.f;
    #pragma unroll
    for (int j = 0; j < 8; j++) { s += d_psum[c*8+j]; q += d_psq[c*8+j]; }
    float mean = s * (1.f / NPIX_PER_CH);
    float var  = q * (1.f / NPIX_PER_CH) - mean*mean;
    ga = gamma[c] * rsqrtf(var + BN_EPS);
    gb = beta[c] - mean * ga;
}

// ---------------- L0: stats + SA weights + fp16 B prepack ----------------
__global__ void k_init(const float* __restrict__ x, const float* __restrict__ cw,
                       const float* __restrict__ sw) {
    int bx = blockIdx.x, tid = threadIdx.x;
    if (bx < 768) {                      // BN statistics
        int c = bx >> 3, part = bx & 7;
        float s = 0.f, q = 0.f;
        #pragma unroll
        for (int b2 = 0; b2 < 2; b2++) {
            const float4* p4 = (const float4*)(x + (size_t)((part*2 + b2)*NC + c) * (NR*NHW));
            for (int i = tid; i < NR*NHW/4; i += 256) {
                float4 v = p4[i];
                s += v.x + v.y + v.z + v.w;
                q += v.x*v.x + v.y*v.y + v.z*v.z + v.w*v.w;
            }
        }
        __shared__ float rs[8], rq[8];
        int wid = tid >> 5, lane = tid & 31;
        s = warpSum(s); q = warpSum(q);
        if (lane == 0) { rs[wid] = s; rq[wid] = q; }
        __syncthreads();
        if (tid == 0) {
            float S = 0.f, Q = 0.f;
            #pragma unroll
            for (int j = 0; j < 8; j++) { S += rs[j]; Q += rq[j]; }
            d_psum[c*8 + part] = S;
            d_psq [c*8 + part] = Q;
        }
    } else if (bx < 775) {               // SA weight transform
        int idx = (bx - 768)*256 + tid;
        if (idx >= NR*2*NR*49) return;
        int ij = idx % 49; int t = idx / 49;
        int r  = t & 3;    t >>= 2;
        int p  = t & 1;    int h = t >> 1;
        int i = ij / 7, j = ij % 7;
        int rs = (r - h) & 3;
        int si, sj;
        switch (h) {
            case 0:  si = i;     sj = j;     break;
            case 1:  si = j;     sj = 6 - i; break;
            case 2:  si = 6 - i; sj = 6 - j; break;
            default: si = 6 - j; sj = i;     break;
        }
        d_wsa[idx] = sw[(p*NR + rs)*49 + si*7 + sj];
    } else {                             // fp16 B prepack into per-lane fragment u64s
        int idx = (bx - 775)*256 + tid;
        if (idx >= WB_TOTAL) return;
        int lane = idx & 31; int t = idx >> 5;
        int nt   = t % 6;    t /= 6;
        int tap  = t % 9;    t /= 9;
        int chunk = t % NCHUNK;
        int h = t / NCHUNK;
        int n = nt*8 + (lane >> 2);
        int k0 = (lane & 3)*2;
        int i = tap / 3, j = tap % 3, si, sj;
        switch (h) {
            case 0:  si = i;     sj = j;     break;
            case 1:  si = j;     sj = 2 - i; break;
            case 2:  si = 2 - i; sj = 2 - j; break;
            default: si = 2 - j; sj = i;     break;
        }
        unsigned long long pk = 0;
        #pragma unroll
        for (int q = 0; q < 4; q++) {
            int kk = k0 + (q & 1) + (q >> 1)*8;
            int cr = chunk*CHC + kk;
            int c = cr >> 2, r = cr & 3;
            int rs = (r - h) & 3;
            float w = cw[(((n*NC + c)*NR + rs)*3 + si)*3 + sj];
            unsigned short bits = __half_as_ushort(__float2half(w));
            pk |= (unsigned long long)bits << (q*16);
        }
        d_wb[idx] = pk;
    }
}

// ---------------- L1: spatial squeeze + channel pooling ----------------
#define PB 18
__global__ void k_pool(const float* __restrict__ x, const float* __restrict__ gamma,
                       const float* __restrict__ beta) {
    int bx = blockIdx.x, tid = threadIdx.x;
    if (bx < NB*NCR) {
        int id = bx;
        int c = (id >> 2) % NC;
        float ga, gb;
        bn_affine(c, gamma, beta, ga, gb);
        const float* p = x + (size_t)id * NHW;
        float s = 0.f, m = 0.f;
        for (int i = tid; i < NHW; i += 256) {
            float v = fmaxf(fmaf(ga, p[i], gb), 0.f);
            s += v; m = fmaxf(m, v);
        }
        __shared__ float rs[8], rm[8];
        int wid = tid >> 5, lane = tid & 31;
        s = warpSum(s); m = warpMax(m);
        if (lane == 0) { rs[wid] = s; rm[wid] = m; }
        __syncthreads();
        if (tid == 0) {
            float S = 0.f, M = 0.f;
            #pragma unroll
            for (int j = 0; j < 8; j++) { S += rs[j]; M = fmaxf(M, rm[j]); }
            d_savg[id] = S * (1.f / NHW);
            d_smax[id] = M;
        }
    } else {
        __shared__ float sga[NC], sgb[NC];
        if (tid < NC) bn_affine(tid, gamma, beta, sga[tid], sgb[tid]);
        __syncthreads();
        int idx = bx - NB*NCR;
        int pb = idx % PB, br = idx / PB;
        int b = br >> 2, r = br & 3;
        int p = pb*256 + tid;
        if (p >= NHW) return;
        float s = 0.f, m = 0.f;
        const float* xb = x + (size_t)(b*NCR + r) * NHW + p;
        #pragma unroll 4
        for (int c = 0; c < NC; c++) {
            float v = fmaxf(fmaf(sga[c], xb[(size_t)(c*4) * NHW], sgb[c]), 0.f);
            s += v; m = fmaxf(m, v);
        }
        d_um[br*NHW + p] = s * (1.f / NC);
        d_ux[br*NHW + p] = m;
    }
}

// ---------------- L2: merged channel-attention MLP + spatial attention ------------
__global__ void k_att(const float* __restrict__ fc1, const float* __restrict__ fc2) {
    int bx = blockIdx.x, tid = threadIdx.x;
    if (bx < NB) {
        int b = bx;
        __shared__ float sA[NCR], sM[NCR], f1[2*NCR], f2[NC*8];
        __shared__ float dred[16], hsum[8];
        for (int i = tid; i < NCR; i += 256) { sA[i] = d_savg[b*NCR + i]; sM[i] = d_smax[b*NCR + i]; }
        for (int i = tid; i < 2*NCR; i += 256) { f1[i] = fc1[i]; f2[i] = fc2[i]; }
        __syncthreads();
        int wid = tid >> 5, lane = tid & 31;
        #pragma unroll
        for (int dd = 0; dd < 2; dd++) {
            int d = wid*2 + dd;
            int sel = d & 1, he = d >> 1;
            int h = he >> 1, e = he & 1;
            const float* sv = sel ? sM : sA;
            float sum = 0.f;
            for (int k = lane; k < NCR; k += 32) {
                int r = k & 3;
                sum += sv[k] * f1[e*NCR + (k & ~3) + (((r - h) & 3))];
            }
            sum = warpSum(sum);
            if (lane == 0) dred[d] = fmaxf(sum, 0.f);
        }
        __syncthreads();
        if (tid < 8) hsum[tid] = dred[tid*2] + dred[tid*2 + 1];
        __syncthreads();
        for (int idx = tid; idx < NR*NCR; idx += 256) {
            int h = idx / NCR, cr = idx % NCR;
            int c = cr >> 2, r = cr & 3;
            int rs = (r - h) & 3;
            float v = hsum[h*2 + 0] * f2[c*8 + rs]
                    + hsum[h*2 + 1] * f2[c*8 + 4 + rs];
            d_ca[b*(NR*NCR) + idx] = sigmoidf(v);
        }
    } else {
        __shared__ float ws[2*NR*49];
        int idx = bx - NB;
        int pb = idx % PB, bh = idx / PB;
        int b = bh >> 2, h = bh & 3;
        for (int i = tid; i < 2*NR*49; i += 256) ws[i] = d_wsa[h*(2*NR*49) + i];
        __syncthreads();
        int p = pb*256 + tid;
        if (p >= NHW) return;
        int y = p / NH, x0 = p % NH;
        float s = 0.f;
        #pragma unroll
        for (int p2 = 0; p2 < 2; p2++) {
            const float* ubase = p2 ? d_ux : d_um;
            #pragma unroll
            for (int r = 0; r < NR; r++) {
                const float* u = ubase + (size_t)(b*4 + r) * NHW;
                const float* w = ws + (p2*4 + r)*49;
                #pragma unroll
                for (int i = 0; i < 7; i++) {
                    int Y = y + i - 3;
                    if (Y < 0 || Y >= NH) continue;
                    #pragma unroll
                    for (int j = 0; j < 7; j++) {
                        int X = x0 + j - 3;
                        if (X < 0 || X >= NH) continue;
                        s += u[Y*NH + X] * w[i*7 + j];
                    }
                }
            }
        }
        d_sp[bh*NHW + p] = sigmoidf(s);
    }
}

// ---------------- L3 (PROFILED): gated conv, 2-term fp16 HMMA, swizzled smem ------
// Block: 256 thr = 8 warps; M=128 px (2 output rows x 64), N=48, shift-trick taps.
// A tile: 64B per pixel = 4x16B units [hi k0-7][hi k8-15][lo k0-7][lo k8-15],
// 16B-unit index swizzled by off ^= (off>>3)&0x30 (SW64 pattern) -> conflict-free LDSM.
__global__ __launch_bounds__(256, 3) void k_conv(const float* __restrict__ x,
                                                 const float* __restrict__ gamma,
                                                 const float* __restrict__ beta,
                                                 float* __restrict__ out) {
    __shared__ __align__(1024) unsigned long long sB[WB_PER_CHUNK];   // 13824 B
    __shared__ __align__(1024) uint4 sA4[4*66*4];                     // 16896 B packed fp16
    __shared__ float sF[CHC*264];                                     // 16896 B gated floats
    __shared__ float s_sp[4*66];
    __shared__ float s_ga[NCR], s_gb[NCR];
    __shared__ float s_gac[NC], s_gbc[NC];

    int ytile = blockIdx.x, bh = blockIdx.y;
    int b = bh >> 2, h = bh & 3;
    int y0 = ytile * 2;
    int tid = threadIdx.x, lane = tid & 31, w = tid >> 5;

    if (tid < NC) bn_affine(tid, gamma, beta, s_gac[tid], s_gbc[tid]);
    for (int i = tid; i < 4*66; i += 256) {
        int row = i / 66, col = i - row*66;
        s_sp[i] = d_sp[bh*NHW + (y0 + row)*NH + col];
    }
    __syncthreads();
    for (int i = tid; i < NCR; i += 256) {
        float ca = d_ca[bh*NCR + i];
        int c = i >> 2;
        s_ga[i] = s_gac[c] * ca;
        s_gb[i] = s_gbc[c] * ca;
    }

    float acc[6][4];
    #pragma unroll
    for (int nt = 0; nt < 6; nt++)
        #pragma unroll
        for (int q = 0; q < 4; q++) acc[nt][q] = 0.f;

    // per-lane fragment geometry (verified rounds 7-8)
    int matrix = lane >> 3, mrow = lane & 7;
    int fragrow = ((matrix & 1) << 3) + mrow;
    int colhalf = matrix >> 1;
    int px_x = (w & 3)*16 + fragrow;
    int px_y = (w >> 2);
    int pxbase = px_y*66 + px_x;
    uint32_t sA_base = smem_u32(sA4);

    const float* xb = x + (size_t)b * NCR * NHW;

    for (int chunk = 0; chunk < NCHUNK; chunk++) {
        __syncthreads();
        // stage B chunk (13824 B, conflict-free)
        {
            const uint4* src = (const uint4*)(d_wb + (size_t)(h*NCHUNK + chunk)*WB_PER_CHUNK);
            #pragma unroll
            for (int i = tid; i < WB_PER_CHUNK/2; i += 256) ((uint4*)sB)[i] = src[i];
        }
        // phase A: gated floats into sF[ch][px] (coalesced LDG, conflict-free STS.32)
        int cr0 = chunk * CHC;
        for (int i = tid; i < CHC*264; i += 256) {
            int ch = i / 264; int px = i - ch*264;
            int row = px / 66, col = px - row*66;
            int cr = cr0 + ch;
            float v = xb[(size_t)cr * NHW + (y0 + row)*NH + col];
            sF[i] = fmaxf(fmaf(s_ga[cr], v, s_gb[cr]), 0.f) * s_sp[px];
        }
        __syncthreads();
        // phase B: convert + pack, swizzled 16B stores (2 threads per pixel)
        for (int s = tid; s < 528; s += 256) {
            int p = s >> 1, hh = s & 1;
            const float* f = sF + hh*8*264 + p;
            uint32_t hiw[4], low[4];
            #pragma unroll
            for (int j = 0; j < 4; j++) {
                float v0 = f[(2*j)*264], v1 = f[(2*j+1)*264];
                __half h0 = __float2half(v0), h1 = __float2half(v1);
                __half l0 = __float2half(v0 - __half2float(h0));
                __half l1 = __float2half(v1 - __half2float(h1));
                hiw[j] = (uint32_t)__half_as_ushort(h0) | ((uint32_t)__half_as_ushort(h1) << 16);
                low[j] = (uint32_t)__half_as_ushort(l0) | ((uint32_t)__half_as_ushort(l1) << 16);
            }
            uint32_t offh = (uint32_t)(p*64 + hh*16);       offh ^= (offh >> 3) & 0x30;
            uint32_t offl = (uint32_t)(p*64 + (hh + 2)*16); offl ^= (offl >> 3) & 0x30;
            *(uint4*)((char*)sA4 + offh) = make_uint4(hiw[0], hiw[1], hiw[2], hiw[3]);
            *(uint4*)((char*)sA4 + offl) = make_uint4(low[0], low[1], low[2], low[3]);
        }
        __syncthreads();
        #pragma unroll
        for (int tap = 0; tap < 9; tap++) {
            const int di = tap / 3, dj = tap % 3;
            uint32_t off = (uint32_t)((pxbase + di*66 + dj)*64 + colhalf*16);
            off ^= (off >> 3) & 0x30;
            uint32_t addr = sA_base + off;
            uint32_t h0, h1, h2, h3, l0, l1, l2, l3;
            LDSM_X4(h0, h1, h2, h3, addr);            // hi fragment
            LDSM_X4(l0, l1, l2, l3, addr ^ 32u);      // lo fragment (swizzle-consistent)
            const unsigned long long* bp = sB + tap*192;
            #pragma unroll
            for (int nt = 0; nt < 6; nt++) {
                unsigned long long b2 = bp[nt*32 + lane];
                uint32_t b0 = (uint32_t)b2, b1 = (uint32_t)(b2 >> 32);
                MMA16816F16(acc[nt], h0, h1, h2, h3, b0, b1);   // hi * w
                MMA16816F16(acc[nt], l0, l1, l2, l3, b0, b1);   // lo * w
            }
        }
    }

    // epilogue: C fragment -> out[b, o, h, y, x]
    int ox = (w & 3)*16 + (lane >> 2);
    int oy = y0 + (w >> 2);
    #pragma unroll
    for (int nt = 0; nt < 6; nt++) {
        int o0 = nt*8 + (lane & 3)*2;
        size_t i0 = (((size_t)(b*144 + o0))*4 + h)*4096 + (size_t)oy*64;
        out[i0 + ox]               = acc[nt][0];
        out[i0 + 16384 + ox]       = acc[nt][1];
        out[i0 + ox + 8]           = acc[nt][2];
        out[i0 + 16384 + ox + 8]   = acc[nt][3];
    }
}

// ---------------- L4: dense concat crop ----------------
__global__ void k_crop(const float* __restrict__ x, float* __restrict__ out) {
    int idx = blockIdx.x*256 + threadIdx.x;
    if (idx >= NB*NC*NR*64*16) return;
    int q   = idx & 15;
    int y   = (idx >> 4) & 63;
    int brc = idx >> 10;
    int b   = brc / NCR;
    int crr = brc % NCR;
    int c   = crr >> 2, r = crr & 3;
    const float* src = x + (size_t)brc * NHW + (size_t)(y + 1)*NH + (q*4 + 1);
    float4 v = make_float4(src[0], src[1], src[2], src[3]);
    size_t off = (((size_t)b*144 + 48 + c)*4 + r)*4096 + (size_t)y*64 + q*4;
    *(float4*)(out + off) = v;
}

// ---------------- launch: k_conv is launch index 3 (the ncu-captured one) ---------
extern "C" void kernel_launch(void* const* d_in, const int* in_sizes, int n_in,
                              void* d_out, int out_size) {
    const float* x     = (const float*)d_in[0];
    const float* gamma = (const float*)d_in[1];
    const float* beta  = (const float*)d_in[2];
    const float* fc1   = (const float*)d_in[3];
    const float* fc2   = (const float*)d_in[4];
    const float* sa    = (const float*)d_in[5];
    const float* cw    = (const float*)d_in[6];
    float* out = (float*)d_out;
    (void)in_sizes; (void)n_in; (void)out_size;

    int init_blocks = 775 + (WB_TOTAL + 255)/256;              // 775 + 648
    k_init<<<init_blocks, 256>>>(x, cw, sa);                   // 0
    k_pool<<<NB*NCR + PB*NB*NR, 256>>>(x, gamma, beta);        // 1
    k_att <<<NB + PB*NB*NR, 256>>>(fc1, fc2);                  // 2
    k_conv<<<dim3(32, NB*NR), 256>>>(x, gamma, beta, out);     // 3  <- profiled
    k_crop<<<(NB*NC*NR*64*16 + 255)/256, 256>>>(x, out);       // 4
}

// round 10
// speedup vs baseline: 4.9275x; 2.1804x over previous
#include <cuda_runtime.h>
#include <cuda_fp16.h>
#include <math.h>
#include <stdint.h>

#define NB 16
#define NC 96
#define NR 4
#define NO 48
#define NH 66
#define NHW (NH*NH)          // 4356
#define NCR (NC*NR)          // 384
#define BN_EPS 2e-5f
#define NPIX_PER_CH (NB*NR*NHW)

// ---- conv GEMM config ----
#define CHC 16                          // channels per chunk
#define NCHUNK 24                       // 384/16
#define WB_PER_CHUNK (9*6*32)           // taps x ntiles x lanes (u64 each) = 1728
#define WB_TOTAL (NR*NCHUNK*WB_PER_CHUNK)   // 165888
#define ROWS 4                          // output rows per block
#define IR (ROWS+2)                     // input rows per block = 6
#define IPX (IR*66)                     // input pixels per block = 396

// ---------------- scratch (device globals) ----------------
__device__ float d_psum[NC*8];
__device__ float d_psq[NC*8];
__device__ float d_savg[NB*NCR];
__device__ float d_smax[NB*NCR];
__device__ float d_ca[NB*NR*NCR];
__device__ float d_um[NB*NR*NHW];
__device__ float d_ux[NB*NR*NHW];
__device__ float d_sp[NB*NR*NHW];
__device__ float d_wsa[NR*2*NR*49];
__device__ unsigned long long d_wb[WB_TOTAL];   // mma-fragment-ordered fp16 weights

__device__ __forceinline__ uint32_t smem_u32(const void* p) {
    uint32_t a;
    asm("{ .reg .u64 t; cvta.to.shared.u64 t, %1; cvt.u32.u64 %0, t; }" : "=r"(a) : "l"(p));
    return a;
}
__device__ __forceinline__ float warpSum(float v) {
    #pragma unroll
    for (int o = 16; o; o >>= 1) v += __shfl_down_sync(0xffffffffu, v, o);
    return v;
}
__device__ __forceinline__ float warpMax(float v) {
    #pragma unroll
    for (int o = 16; o; o >>= 1) v = fmaxf(v, __shfl_down_sync(0xffffffffu, v, o));
    return v;
}
__device__ __forceinline__ float sigmoidf(float v) { return 1.f / (1.f + expf(-v)); }

#define LDSM_X4(r0, r1, r2, r3, addr) \
    asm volatile("ldmatrix.sync.aligned.m8n8.x4.shared.b16 {%0,%1,%2,%3}, [%4];" \
        : "=r"(r0), "=r"(r1), "=r"(r2), "=r"(r3) : "r"(addr))

#define MMA16816F16(c, a0, a1, a2, a3, b0, b1) \
    asm volatile("mma.sync.aligned.m16n8k16.row.col.f32.f16.f16.f32 " \
        "{%0,%1,%2,%3}, {%4,%5,%6,%7}, {%8,%9}, {%0,%1,%2,%3};" \
        : "+f"((c)[0]), "+f"((c)[1]), "+f"((c)[2]), "+f"((c)[3]) \
        : "r"(a0), "r"(a1), "r"(a2), "r"(a3), "r"(b0), "r"(b1))

// compute BN affine for channel c from partial sums
__device__ __forceinline__ void bn_affine(int c, const float* gamma, const float* beta,
                                          float& ga, float& gb) {
    float s = 0.f, q = 0.f;
    #pragma unroll
    for (int j = 0; j < 8; j++) { s += d_psum[c*8+j]; q += d_psq[c*8+j]; }
    float mean = s * (1.f / NPIX_PER_CH);
    float var  = q * (1.f / NPIX_PER_CH) - mean*mean;
    ga = gamma[c] * rsqrtf(var + BN_EPS);
    gb = beta[c] - mean * ga;
}

// ---------------- L0: stats + SA weights + fp16 B prepack ----------------
__global__ void k_init(const float* __restrict__ x, const float* __restrict__ cw,
                       const float* __restrict__ sw) {
    int bx = blockIdx.x, tid = threadIdx.x;
    if (bx < 768) {                      // BN statistics
        int c = bx >> 3, part = bx & 7;
        float s = 0.f, q = 0.f;
        #pragma unroll
        for (int b2 = 0; b2 < 2; b2++) {
            const float4* p4 = (const float4*)(x + (size_t)((part*2 + b2)*NC + c) * (NR*NHW));
            for (int i = tid; i < NR*NHW/4; i += 256) {
                float4 v = p4[i];
                s += v.x + v.y + v.z + v.w;
                q += v.x*v.x + v.y*v.y + v.z*v.z + v.w*v.w;
            }
        }
        __shared__ float rs[8], rq[8];
        int wid = tid >> 5, lane = tid & 31;
        s = warpSum(s); q = warpSum(q);
        if (lane == 0) { rs[wid] = s; rq[wid] = q; }
        __syncthreads();
        if (tid == 0) {
            float S = 0.f, Q = 0.f;
            #pragma unroll
            for (int j = 0; j < 8; j++) { S += rs[j]; Q += rq[j]; }
            d_psum[c*8 + part] = S;
            d_psq [c*8 + part] = Q;
        }
    } else if (bx < 775) {               // SA weight transform
        int idx = (bx - 768)*256 + tid;
        if (idx >= NR*2*NR*49) return;
        int ij = idx % 49; int t = idx / 49;
        int r  = t & 3;    t >>= 2;
        int p  = t & 1;    int h = t >> 1;
        int i = ij / 7, j = ij % 7;
        int rs = (r - h) & 3;
        int si, sj;
        switch (h) {
            case 0:  si = i;     sj = j;     break;
            case 1:  si = j;     sj = 6 - i; break;
            case 2:  si = 6 - i; sj = 6 - j; break;
            default: si = 6 - j; sj = i;     break;
        }
        d_wsa[idx] = sw[(p*NR + rs)*49 + si*7 + sj];
    } else {                             // fp16 B prepack into per-lane fragment u64s
        int idx = (bx - 775)*256 + tid;
        if (idx >= WB_TOTAL) return;
        int lane = idx & 31; int t = idx >> 5;
        int nt   = t % 6;    t /= 6;
        int tap  = t % 9;    t /= 9;
        int chunk = t % NCHUNK;
        int h = t / NCHUNK;
        int n = nt*8 + (lane >> 2);
        int k0 = (lane & 3)*2;
        int i = tap / 3, j = tap % 3, si, sj;
        switch (h) {
            case 0:  si = i;     sj = j;     break;
            case 1:  si = j;     sj = 2 - i; break;
            case 2:  si = 2 - i; sj = 2 - j; break;
            default: si = 2 - j; sj = i;     break;
        }
        unsigned long long pk = 0;
        #pragma unroll
        for (int q = 0; q < 4; q++) {
            int kk = k0 + (q & 1) + (q >> 1)*8;
            int cr = chunk*CHC + kk;
            int c = cr >> 2, r = cr & 3;
            int rs = (r - h) & 3;
            float w = cw[(((n*NC + c)*NR + rs)*3 + si)*3 + sj];
            unsigned short bits = __half_as_ushort(__float2half(w));
            pk |= (unsigned long long)bits << (q*16);
        }
        d_wb[idx] = pk;
    }
}

// ---------------- L1: spatial squeeze + channel pooling ----------------
#define PB 18
__global__ void k_pool(const float* __restrict__ x, const float* __restrict__ gamma,
                       const float* __restrict__ beta) {
    int bx = blockIdx.x, tid = threadIdx.x;
    if (bx < NB*NCR) {
        int id = bx;
        int c = (id >> 2) % NC;
        float ga, gb;
        bn_affine(c, gamma, beta, ga, gb);
        const float* p = x + (size_t)id * NHW;
        float s = 0.f, m = 0.f;
        for (int i = tid; i < NHW; i += 256) {
            float v = fmaxf(fmaf(ga, p[i], gb), 0.f);
            s += v; m = fmaxf(m, v);
        }
        __shared__ float rs[8], rm[8];
        int wid = tid >> 5, lane = tid & 31;
        s = warpSum(s); m = warpMax(m);
        if (lane == 0) { rs[wid] = s; rm[wid] = m; }
        __syncthreads();
        if (tid == 0) {
            float S = 0.f, M = 0.f;
            #pragma unroll
            for (int j = 0; j < 8; j++) { S += rs[j]; M = fmaxf(M, rm[j]); }
            d_savg[id] = S * (1.f / NHW);
            d_smax[id] = M;
        }
    } else {
        __shared__ float sga[NC], sgb[NC];
        if (tid < NC) bn_affine(tid, gamma, beta, sga[tid], sgb[tid]);
        __syncthreads();
        int idx = bx - NB*NCR;
        int pb = idx % PB, br = idx / PB;
        int b = br >> 2, r = br & 3;
        int p = pb*256 + tid;
        if (p >= NHW) return;
        float s = 0.f, m = 0.f;
        const float* xb = x + (size_t)(b*NCR + r) * NHW + p;
        #pragma unroll 4
        for (int c = 0; c < NC; c++) {
            float v = fmaxf(fmaf(sga[c], xb[(size_t)(c*4) * NHW], sgb[c]), 0.f);
            s += v; m = fmaxf(m, v);
        }
        d_um[br*NHW + p] = s * (1.f / NC);
        d_ux[br*NHW + p] = m;
    }
}

// ---------------- L2: merged channel-attention MLP + spatial attention ------------
__global__ void k_att(const float* __restrict__ fc1, const float* __restrict__ fc2) {
    int bx = blockIdx.x, tid = threadIdx.x;
    if (bx < NB) {
        int b = bx;
        __shared__ float sA[NCR], sM[NCR], f1[2*NCR], f2[NC*8];
        __shared__ float dred[16], hsum[8];
        for (int i = tid; i < NCR; i += 256) { sA[i] = d_savg[b*NCR + i]; sM[i] = d_smax[b*NCR + i]; }
        for (int i = tid; i < 2*NCR; i += 256) { f1[i] = fc1[i]; f2[i] = fc2[i]; }
        __syncthreads();
        int wid = tid >> 5, lane = tid & 31;
        #pragma unroll
        for (int dd = 0; dd < 2; dd++) {
            int d = wid*2 + dd;
            int sel = d & 1, he = d >> 1;
            int h = he >> 1, e = he & 1;
            const float* sv = sel ? sM : sA;
            float sum = 0.f;
            for (int k = lane; k < NCR; k += 32) {
                int r = k & 3;
                sum += sv[k] * f1[e*NCR + (k & ~3) + (((r - h) & 3))];
            }
            sum = warpSum(sum);
            if (lane == 0) dred[d] = fmaxf(sum, 0.f);
        }
        __syncthreads();
        if (tid < 8) hsum[tid] = dred[tid*2] + dred[tid*2 + 1];
        __syncthreads();
        for (int idx = tid; idx < NR*NCR; idx += 256) {
            int h = idx / NCR, cr = idx % NCR;
            int c = cr >> 2, r = cr & 3;
            int rs = (r - h) & 3;
            float v = hsum[h*2 + 0] * f2[c*8 + rs]
                    + hsum[h*2 + 1] * f2[c*8 + 4 + rs];
            d_ca[b*(NR*NCR) + idx] = sigmoidf(v);
        }
    } else {
        __shared__ float ws[2*NR*49];
        int idx = bx - NB;
        int pb = idx % PB, bh = idx / PB;
        int b = bh >> 2, h = bh & 3;
        for (int i = tid; i < 2*NR*49; i += 256) ws[i] = d_wsa[h*(2*NR*49) + i];
        __syncthreads();
        int p = pb*256 + tid;
        if (p >= NHW) return;
        int y = p / NH, x0 = p % NH;
        float s = 0.f;
        #pragma unroll
        for (int p2 = 0; p2 < 2; p2++) {
            const float* ubase = p2 ? d_ux : d_um;
            #pragma unroll
            for (int r = 0; r < NR; r++) {
                const float* u = ubase + (size_t)(b*4 + r) * NHW;
                const float* w = ws + (p2*4 + r)*49;
                #pragma unroll
                for (int i = 0; i < 7; i++) {
                    int Y = y + i - 3;
                    if (Y < 0 || Y >= NH) continue;
                    #pragma unroll
                    for (int j = 0; j < 7; j++) {
                        int X = x0 + j - 3;
                        if (X < 0 || X >= NH) continue;
                        s += u[Y*NH + X] * w[i*7 + j];
                    }
                }
            }
        }
        d_sp[bh*NHW + p] = sigmoidf(s);
    }
}

// ---------------- L3 (PROFILED): gated conv, 2-term fp16 HMMA, M=256/block --------
// Block: 256 thr = 8 warps; 4 output rows x 64 px (M=256), N=48; warp owns 2 m16 tiles.
// A tile: 64B per input pixel = 4x16B units [hi k0-7][hi k8-15][lo k0-7][lo k8-15],
// 16B-unit swizzle off ^= (off>>3)&0x30 -> conflict-free LDSM + STS.128.
__global__ __launch_bounds__(256, 2) void k_conv(const float* __restrict__ x,
                                                 const float* __restrict__ gamma,
                                                 const float* __restrict__ beta,
                                                 float* __restrict__ out) {
    __shared__ __align__(1024) unsigned long long sB[WB_PER_CHUNK];   // 13824 B
    __shared__ __align__(1024) uint4 sA4[IPX*4];                      // 25344 B packed fp16
    __shared__ float s_sp[IPX];
    __shared__ float s_ga[NCR], s_gb[NCR];
    __shared__ float s_gac[NC], s_gbc[NC];

    int ytile = blockIdx.x, bh = blockIdx.y;
    int b = bh >> 2, h = bh & 3;
    int y0 = ytile * ROWS;
    int tid = threadIdx.x, lane = tid & 31, w = tid >> 5;

    if (tid < NC) bn_affine(tid, gamma, beta, s_gac[tid], s_gbc[tid]);
    for (int i = tid; i < IPX; i += 256) {
        int row = i / 66, col = i - row*66;
        s_sp[i] = d_sp[bh*NHW + (y0 + row)*NH + col];
    }
    __syncthreads();
    for (int i = tid; i < NCR; i += 256) {
        float ca = d_ca[bh*NCR + i];
        int c = i >> 2;
        s_ga[i] = s_gac[c] * ca;
        s_gb[i] = s_gbc[c] * ca;
    }

    float acc[2][6][4];
    #pragma unroll
    for (int t = 0; t < 2; t++)
        #pragma unroll
        for (int nt = 0; nt < 6; nt++)
            #pragma unroll
            for (int q = 0; q < 4; q++) acc[t][nt][q] = 0.f;

    // per-lane fragment geometry; warp owns m16 tiles t0=2w, t1=2w+1
    int matrix = lane >> 3, mrow = lane & 7;
    int fragrow = ((matrix & 1) << 3) + mrow;
    int colhalf = matrix >> 1;
    uint32_t sA_base = smem_u32(sA4);
    uint32_t addrA[2][9];                 // chunk-invariant swizzled hi-frag addresses
    #pragma unroll
    for (int t = 0; t < 2; t++) {
        int tt = 2*w + t;
        int pxb = (tt >> 2)*66 + (tt & 3)*16 + fragrow;
        #pragma unroll
        for (int tap = 0; tap < 9; tap++) {
            int di = tap / 3, dj = tap % 3;
            uint32_t off = (uint32_t)((pxb + di*66 + dj)*64 + colhalf*16);
            off ^= (off >> 3) & 0x30;
            addrA[t][tap] = sA_base + off;
        }
    }

    const float* xb = x + (size_t)b * NCR * NHW;

    for (int chunk = 0; chunk < NCHUNK; chunk++) {
        int cr0 = chunk * CHC;
        __syncthreads();
        // stage B chunk (13824 B, conflict-free)
        {
            const uint4* src = (const uint4*)(d_wb + (size_t)(h*NCHUNK + chunk)*WB_PER_CHUNK);
            #pragma unroll
            for (int i = tid; i < WB_PER_CHUNK/2; i += 256) ((uint4*)sB)[i] = src[i];
        }
        // build A: gate + split-fp16 straight from gmem, swizzled STS.128
        for (int s = tid; s < 2*IPX; s += 256) {
            int hh = s / IPX, p = s - hh*IPX;
            int row = p / 66, col = p - row*66;
            const float* xp = xb + (size_t)(cr0 + hh*8) * NHW + (y0 + row)*NH + col;
            float sp = s_sp[p];
            uint32_t hiw[4], low[4];
            #pragma unroll
            for (int j = 0; j < 4; j++) {
                int cra = cr0 + hh*8 + 2*j;
                float v0 = fmaxf(fmaf(s_ga[cra],     xp[(size_t)(2*j)*NHW],     s_gb[cra]),     0.f) * sp;
                float v1 = fmaxf(fmaf(s_ga[cra + 1], xp[(size_t)(2*j + 1)*NHW], s_gb[cra + 1]), 0.f) * sp;
                __half h0 = __float2half(v0), h1 = __float2half(v1);
                __half l0 = __float2half(v0 - __half2float(h0));
                __half l1 = __float2half(v1 - __half2float(h1));
                hiw[j] = (uint32_t)__half_as_ushort(h0) | ((uint32_t)__half_as_ushort(h1) << 16);
                low[j] = (uint32_t)__half_as_ushort(l0) | ((uint32_t)__half_as_ushort(l1) << 16);
            }
            uint32_t offh = (uint32_t)(p*64 + hh*16);       offh ^= (offh >> 3) & 0x30;
            uint32_t offl = (uint32_t)(p*64 + (hh + 2)*16); offl ^= (offl >> 3) & 0x30;
            *(uint4*)((char*)sA4 + offh) = make_uint4(hiw[0], hiw[1], hiw[2], hiw[3]);
            *(uint4*)((char*)sA4 + offl) = make_uint4(low[0], low[1], low[2], low[3]);
        }
        __syncthreads();
        #pragma unroll
        for (int tap = 0; tap < 9; tap++) {
            uint32_t a0 = addrA[0][tap], a1 = addrA[1][tap];
            uint32_t h00, h01, h02, h03, l00, l01, l02, l03;
            uint32_t h10, h11, h12, h13, l10, l11, l12, l13;
            LDSM_X4(h00, h01, h02, h03, a0);
            LDSM_X4(l00, l01, l02, l03, a0 ^ 32u);
            LDSM_X4(h10, h11, h12, h13, a1);
            LDSM_X4(l10, l11, l12, l13, a1 ^ 32u);
            const unsigned long long* bp = sB + tap*192 + lane;
            #pragma unroll
            for (int nt = 0; nt < 6; nt++) {
                unsigned long long b2 = bp[nt*32];
                uint32_t b0 = (uint32_t)b2, b1 = (uint32_t)(b2 >> 32);
                MMA16816F16(acc[0][nt], h00, h01, h02, h03, b0, b1);
                MMA16816F16(acc[0][nt], l00, l01, l02, l03, b0, b1);
                MMA16816F16(acc[1][nt], h10, h11, h12, h13, b0, b1);
                MMA16816F16(acc[1][nt], l10, l11, l12, l13, b0, b1);
            }
        }
    }

    // epilogue: C fragments -> out[b, o, h, y, x]
    #pragma unroll
    for (int t = 0; t < 2; t++) {
        int tt = 2*w + t;
        int ox = (tt & 3)*16 + (lane >> 2);
        int oy = y0 + (tt >> 2);
        #pragma unroll
        for (int nt = 0; nt < 6; nt++) {
            int o0 = nt*8 + (lane & 3)*2;
            size_t i0 = (((size_t)(b*144 + o0))*4 + h)*4096 + (size_t)oy*64;
            out[i0 + ox]               = acc[t][nt][0];
            out[i0 + 16384 + ox]       = acc[t][nt][1];
            out[i0 + ox + 8]           = acc[t][nt][2];
            out[i0 + 16384 + ox + 8]   = acc[t][nt][3];
        }
    }
}

// ---------------- L4: dense concat crop ----------------
__global__ void k_crop(const float* __restrict__ x, float* __restrict__ out) {
    int idx = blockIdx.x*256 + threadIdx.x;
    if (idx >= NB*NC*NR*64*16) return;
    int q   = idx & 15;
    int y   = (idx >> 4) & 63;
    int brc = idx >> 10;
    int b   = brc / NCR;
    int crr = brc % NCR;
    int c   = crr >> 2, r = crr & 3;
    const float* src = x + (size_t)brc * NHW + (size_t)(y + 1)*NH + (q*4 + 1);
    float4 v = make_float4(src[0], src[1], src[2], src[3]);
    size_t off = (((size_t)b*144 + 48 + c)*4 + r)*4096 + (size_t)y*64 + q*4;
    *(float4*)(out + off) = v;
}

// ---------------- launch: k_conv is launch index 3 (the ncu-captured one) ---------
extern "C" void kernel_launch(void* const* d_in, const int* in_sizes, int n_in,
                              void* d_out, int out_size) {
    const float* x     = (const float*)d_in[0];
    const float* gamma = (const float*)d_in[1];
    const float* beta  = (const float*)d_in[2];
    const float* fc1   = (const float*)d_in[3];
    const float* fc2   = (const float*)d_in[4];
    const float* sa    = (const float*)d_in[5];
    const float* cw    = (const float*)d_in[6];
    float* out = (float*)d_out;
    (void)in_sizes; (void)n_in; (void)out_size;

    int init_blocks = 775 + (WB_TOTAL + 255)/256;              // 775 + 648
    k_init<<<init_blocks, 256>>>(x, cw, sa);                   // 0
    k_pool<<<NB*NCR + PB*NB*NR, 256>>>(x, gamma, beta);        // 1
    k_att <<<NB + PB*NB*NR, 256>>>(fc1, fc2);                  // 2
    k_conv<<<dim3(16, NB*NR), 256>>>(x, gamma, beta, out);     // 3  <- profiled
    k_crop<<<(NB*NC*NR*64*16 + 255)/256, 256>>>(x, out);       // 4
}

// round 11
// speedup vs baseline: 5.1545x; 1.0461x over previous
#include <cuda_runtime.h>
#include <cuda_fp16.h>
#include <math.h>
#include <stdint.h>

#define NB 16
#define NC 96
#define NR 4
#define NO 48
#define NH 66
#define NHW (NH*NH)          // 4356
#define NCR (NC*NR)          // 384
#define BN_EPS 2e-5f
#define NPIX_PER_CH (NB*NR*NHW)

// ---- conv GEMM config ----
#define CHC 16                          // channels per chunk
#define NCHUNK 24                       // 384/16
#define WB_PER_CHUNK (9*6*32)           // 1728 u64
#define WB_TOTAL (NR*NCHUNK*WB_PER_CHUNK)
#define ROWS 4
#define IR (ROWS+2)
#define IPX (IR*66)                     // 396
#define ABUF_BYTES (IPX*64)             // 25344
#define CONV_DYN (1024 + 2*ABUF_BYTES + 2*WB_PER_CHUNK*8)   // 79360

// ---------------- scratch (device globals) ----------------
__device__ float d_psum[NC*8];
__device__ float d_psq[NC*8];
__device__ float d_savg[NB*NCR];
__device__ float d_smax[NB*NCR];
__device__ float d_ca[NB*NR*NCR];
__device__ float d_um[NB*NR*NHW];
__device__ float d_ux[NB*NR*NHW];
__device__ float d_sp[NB*NR*NHW];
__device__ float d_wsa[NR*2*NR*49];
__device__ unsigned long long d_wb[WB_TOTAL];

__device__ __forceinline__ uint32_t smem_u32(const void* p) {
    uint32_t a;
    asm("{ .reg .u64 t; cvta.to.shared.u64 t, %1; cvt.u32.u64 %0, t; }" : "=r"(a) : "l"(p));
    return a;
}
__device__ __forceinline__ float warpSum(float v) {
    #pragma unroll
    for (int o = 16; o; o >>= 1) v += __shfl_down_sync(0xffffffffu, v, o);
    return v;
}
__device__ __forceinline__ float warpMax(float v) {
    #pragma unroll
    for (int o = 16; o; o >>= 1) v = fmaxf(v, __shfl_down_sync(0xffffffffu, v, o));
    return v;
}
__device__ __forceinline__ float sigmoidf(float v) { return 1.f / (1.f + expf(-v)); }

#define LDSM_X4(r0, r1, r2, r3, addr) \
    asm volatile("ldmatrix.sync.aligned.m8n8.x4.shared.b16 {%0,%1,%2,%3}, [%4];" \
        : "=r"(r0), "=r"(r1), "=r"(r2), "=r"(r3) : "r"(addr))

#define MMA16816F16(c, a0, a1, a2, a3, b0, b1) \
    asm volatile("mma.sync.aligned.m16n8k16.row.col.f32.f16.f16.f32 " \
        "{%0,%1,%2,%3}, {%4,%5,%6,%7}, {%8,%9}, {%0,%1,%2,%3};" \
        : "+f"((c)[0]), "+f"((c)[1]), "+f"((c)[2]), "+f"((c)[3]) \
        : "r"(a0), "r"(a1), "r"(a2), "r"(a3), "r"(b0), "r"(b1))

__device__ __forceinline__ void bn_affine(int c, const float* gamma, const float* beta,
                                          float& ga, float& gb) {
    float s = 0.f, q = 0.f;
    #pragma unroll
    for (int j = 0; j < 8; j++) { s += d_psum[c*8+j]; q += d_psq[c*8+j]; }
    float mean = s * (1.f / NPIX_PER_CH);
    float var  = q * (1.f / NPIX_PER_CH) - mean*mean;
    ga = gamma[c] * rsqrtf(var + BN_EPS);
    gb = beta[c] - mean * ga;
}

// ---------------- L0: stats + SA weights + fp16 B prepack ----------------
__global__ void k_init(const float* __restrict__ x, const float* __restrict__ cw,
                       const float* __restrict__ sw) {
    int bx = blockIdx.x, tid = threadIdx.x;
    if (bx < 768) {
        int c = bx >> 3, part = bx & 7;
        float s = 0.f, q = 0.f;
        #pragma unroll
        for (int b2 = 0; b2 < 2; b2++) {
            const float4* p4 = (const float4*)(x + (size_t)((part*2 + b2)*NC + c) * (NR*NHW));
            for (int i = tid; i < NR*NHW/4; i += 256) {
                float4 v = p4[i];
                s += v.x + v.y + v.z + v.w;
                q += v.x*v.x + v.y*v.y + v.z*v.z + v.w*v.w;
            }
        }
        __shared__ float rs[8], rq[8];
        int wid = tid >> 5, lane = tid & 31;
        s = warpSum(s); q = warpSum(q);
        if (lane == 0) { rs[wid] = s; rq[wid] = q; }
        __syncthreads();
        if (tid == 0) {
            float S = 0.f, Q = 0.f;
            #pragma unroll
            for (int j = 0; j < 8; j++) { S += rs[j]; Q += rq[j]; }
            d_psum[c*8 + part] = S;
            d_psq [c*8 + part] = Q;
        }
    } else if (bx < 775) {
        int idx = (bx - 768)*256 + tid;
        if (idx >= NR*2*NR*49) return;
        int ij = idx % 49; int t = idx / 49;
        int r  = t & 3;    t >>= 2;
        int p  = t & 1;    int h = t >> 1;
        int i = ij / 7, j = ij % 7;
        int rs = (r - h) & 3;
        int si, sj;
        switch (h) {
            case 0:  si = i;     sj = j;     break;
            case 1:  si = j;     sj = 6 - i; break;
            case 2:  si = 6 - i; sj = 6 - j; break;
            default: si = 6 - j; sj = i;     break;
        }
        d_wsa[idx] = sw[(p*NR + rs)*49 + si*7 + sj];
    } else {
        int idx = (bx - 775)*256 + tid;
        if (idx >= WB_TOTAL) return;
        int lane = idx & 31; int t = idx >> 5;
        int nt   = t % 6;    t /= 6;
        int tap  = t % 9;    t /= 9;
        int chunk = t % NCHUNK;
        int h = t / NCHUNK;
        int n = nt*8 + (lane >> 2);
        int k0 = (lane & 3)*2;
        int i = tap / 3, j = tap % 3, si, sj;
        switch (h) {
            case 0:  si = i;     sj = j;     break;
            case 1:  si = j;     sj = 2 - i; break;
            case 2:  si = 2 - i; sj = 2 - j; break;
            default: si = 2 - j; sj = i;     break;
        }
        unsigned long long pk = 0;
        #pragma unroll
        for (int q = 0; q < 4; q++) {
            int kk = k0 + (q & 1) + (q >> 1)*8;
            int cr = chunk*CHC + kk;
            int c = cr >> 2, r = cr & 3;
            int rs = (r - h) & 3;
            float w = cw[(((n*NC + c)*NR + rs)*3 + si)*3 + sj];
            unsigned short bits = __half_as_ushort(__float2half(w));
            pk |= (unsigned long long)bits << (q*16);
        }
        d_wb[idx] = pk;
    }
}

// ---------------- L1: spatial squeeze + channel pooling ----------------
#define PB 18
__global__ void k_pool(const float* __restrict__ x, const float* __restrict__ gamma,
                       const float* __restrict__ beta) {
    int bx = blockIdx.x, tid = threadIdx.x;
    if (bx < NB*NCR) {
        int id = bx;
        int c = (id >> 2) % NC;
        float ga, gb;
        bn_affine(c, gamma, beta, ga, gb);
        const float* p = x + (size_t)id * NHW;
        float s = 0.f, m = 0.f;
        for (int i = tid; i < NHW; i += 256) {
            float v = fmaxf(fmaf(ga, p[i], gb), 0.f);
            s += v; m = fmaxf(m, v);
        }
        __shared__ float rs[8], rm[8];
        int wid = tid >> 5, lane = tid & 31;
        s = warpSum(s); m = warpMax(m);
        if (lane == 0) { rs[wid] = s; rm[wid] = m; }
        __syncthreads();
        if (tid == 0) {
            float S = 0.f, M = 0.f;
            #pragma unroll
            for (int j = 0; j < 8; j++) { S += rs[j]; M = fmaxf(M, rm[j]); }
            d_savg[id] = S * (1.f / NHW);
            d_smax[id] = M;
        }
    } else {
        __shared__ float sga[NC], sgb[NC];
        if (tid < NC) bn_affine(tid, gamma, beta, sga[tid], sgb[tid]);
        __syncthreads();
        int idx = bx - NB*NCR;
        int pb = idx % PB, br = idx / PB;
        int b = br >> 2, r = br & 3;
        int p = pb*256 + tid;
        if (p >= NHW) return;
        float s = 0.f, m = 0.f;
        const float* xb = x + (size_t)(b*NCR + r) * NHW + p;
        #pragma unroll 4
        for (int c = 0; c < NC; c++) {
            float v = fmaxf(fmaf(sga[c], xb[(size_t)(c*4) * NHW], sgb[c]), 0.f);
            s += v; m = fmaxf(m, v);
        }
        d_um[br*NHW + p] = s * (1.f / NC);
        d_ux[br*NHW + p] = m;
    }
}

// ---------------- L2: merged channel-attention MLP + spatial attention ------------
__global__ void k_att(const float* __restrict__ fc1, const float* __restrict__ fc2) {
    int bx = blockIdx.x, tid = threadIdx.x;
    if (bx < NB) {
        int b = bx;
        __shared__ float sA[NCR], sM[NCR], f1[2*NCR], f2[NC*8];
        __shared__ float dred[16], hsum[8];
        for (int i = tid; i < NCR; i += 256) { sA[i] = d_savg[b*NCR + i]; sM[i] = d_smax[b*NCR + i]; }
        for (int i = tid; i < 2*NCR; i += 256) { f1[i] = fc1[i]; f2[i] = fc2[i]; }
        __syncthreads();
        int wid = tid >> 5, lane = tid & 31;
        #pragma unroll
        for (int dd = 0; dd < 2; dd++) {
            int d = wid*2 + dd;
            int sel = d & 1, he = d >> 1;
            int h = he >> 1, e = he & 1;
            const float* sv = sel ? sM : sA;
            float sum = 0.f;
            for (int k = lane; k < NCR; k += 32) {
                int r = k & 3;
                sum += sv[k] * f1[e*NCR + (k & ~3) + (((r - h) & 3))];
            }
            sum = warpSum(sum);
            if (lane == 0) dred[d] = fmaxf(sum, 0.f);
        }
        __syncthreads();
        if (tid < 8) hsum[tid] = dred[tid*2] + dred[tid*2 + 1];
        __syncthreads();
        for (int idx = tid; idx < NR*NCR; idx += 256) {
            int h = idx / NCR, cr = idx % NCR;
            int c = cr >> 2, r = cr & 3;
            int rs = (r - h) & 3;
            float v = hsum[h*2 + 0] * f2[c*8 + rs]
                    + hsum[h*2 + 1] * f2[c*8 + 4 + rs];
            d_ca[b*(NR*NCR) + idx] = sigmoidf(v);
        }
    } else {
        __shared__ float ws[2*NR*49];
        int idx = bx - NB;
        int pb = idx % PB, bh = idx / PB;
        int b = bh >> 2, h = bh & 3;
        for (int i = tid; i < 2*NR*49; i += 256) ws[i] = d_wsa[h*(2*NR*49) + i];
        __syncthreads();
        int p = pb*256 + tid;
        if (p >= NHW) return;
        int y = p / NH, x0 = p % NH;
        float s = 0.f;
        #pragma unroll
        for (int p2 = 0; p2 < 2; p2++) {
            const float* ubase = p2 ? d_ux : d_um;
            #pragma unroll
            for (int r = 0; r < NR; r++) {
                const float* u = ubase + (size_t)(b*4 + r) * NHW;
                const float* w = ws + (p2*4 + r)*49;
                #pragma unroll
                for (int i = 0; i < 7; i++) {
                    int Y = y + i - 3;
                    if (Y < 0 || Y >= NH) continue;
                    #pragma unroll
                    for (int j = 0; j < 7; j++) {
                        int X = x0 + j - 3;
                        if (X < 0 || X >= NH) continue;
                        s += u[Y*NH + X] * w[i*7 + j];
                    }
                }
            }
        }
        d_sp[bh*NHW + p] = sigmoidf(s);
    }
}

// ---------------- L3 (PROFILED): double-buffered 2-term fp16 HMMA conv ------------
// Pipeline per chunk: prefetch next A floats into regs -> MMA(cur) -> copy next B
// -> convert+STS next A. One __syncthreads per chunk; A/B double-buffered.
__global__ __launch_bounds__(256, 2) void k_conv(const float* __restrict__ x,
                                                 const float* __restrict__ gamma,
                                                 const float* __restrict__ beta,
                                                 float* __restrict__ out) {
    extern __shared__ __align__(16) char dyn[];
    __shared__ float s_sp[IPX];
    __shared__ float s_ga[NCR], s_gb[NCR];
    __shared__ float s_gac[NC], s_gbc[NC];

    char* sbase;
    { uintptr_t p0 = (uintptr_t)dyn; p0 = (p0 + 1023) & ~(uintptr_t)1023; sbase = (char*)p0; }
    char* sAc = sbase;                                            // [2][ABUF_BYTES]
    unsigned long long* sBb = (unsigned long long*)(sbase + 2*ABUF_BYTES);  // [2][1728]
    uint4* sB4 = (uint4*)sBb;                                     // [2][864]

    int ytile = blockIdx.x, bh = blockIdx.y;
    int b = bh >> 2, h = bh & 3;
    int y0 = ytile * ROWS;
    int tid = threadIdx.x, lane = tid & 31, w = tid >> 5;

    if (tid < NC) bn_affine(tid, gamma, beta, s_gac[tid], s_gbc[tid]);
    for (int i = tid; i < IPX; i += 256) {
        int row = i / 66, col = i - row*66;
        s_sp[i] = d_sp[bh*NHW + (y0 + row)*NH + col];
    }
    __syncthreads();
    for (int i = tid; i < NCR; i += 256) {
        float ca = d_ca[bh*NCR + i];
        int c = i >> 2;
        s_ga[i] = s_gac[c] * ca;
        s_gb[i] = s_gbc[c] * ca;
    }

    float acc[2][6][4];
    #pragma unroll
    for (int t = 0; t < 2; t++)
        #pragma unroll
        for (int nt = 0; nt < 6; nt++)
            #pragma unroll
            for (int q = 0; q < 4; q++) acc[t][nt][q] = 0.f;

    // fragment geometry
    int matrix = lane >> 3, mrow = lane & 7;
    int fragrow = ((matrix & 1) << 3) + mrow;
    int colhalf = matrix >> 1;
    uint32_t sA_u32 = smem_u32(sAc);
    uint32_t pxoff[2];
    #pragma unroll
    for (int t = 0; t < 2; t++) {
        int tt = 2*w + t;
        int pxb = (tt >> 2)*66 + (tt & 3)*16 + fragrow;
        pxoff[t] = (uint32_t)(pxb*64 + colhalf*16);
    }

    const float* xb = x + (size_t)b * NCR * NHW;
    const uint4* wbsrc = (const uint4*)(d_wb) + (size_t)h * NCHUNK * 864;

    // ---- prologue: build chunk 0 into buffer 0 ----
    for (int i = tid; i < 864; i += 256) sB4[i] = wbsrc[i];
    for (int s = tid; s < 2*IPX; s += 256) {
        int hh = s / IPX, p = s - hh*IPX;
        int row = p / 66, col = p - row*66;
        const float* xp = xb + (size_t)(hh*8) * NHW + (y0 + row)*NH + col;
        float sp = s_sp[p];
        uint32_t hiw[4], low[4];
        #pragma unroll
        for (int j = 0; j < 4; j++) {
            int cra = hh*8 + 2*j;
            float v0 = fmaxf(fmaf(s_ga[cra],     xp[(size_t)(2*j)*NHW],     s_gb[cra]),     0.f) * sp;
            float v1 = fmaxf(fmaf(s_ga[cra + 1], xp[(size_t)(2*j + 1)*NHW], s_gb[cra + 1]), 0.f) * sp;
            __half h0 = __float2half(v0), h1 = __float2half(v1);
            __half l0 = __float2half(v0 - __half2float(h0));
            __half l1 = __float2half(v1 - __half2float(h1));
            hiw[j] = (uint32_t)__half_as_ushort(h0) | ((uint32_t)__half_as_ushort(h1) << 16);
            low[j] = (uint32_t)__half_as_ushort(l0) | ((uint32_t)__half_as_ushort(l1) << 16);
        }
        uint32_t offh = (uint32_t)(p*64 + hh*16);       offh ^= (offh >> 3) & 0x30;
        uint32_t offl = (uint32_t)(p*64 + (hh + 2)*16); offl ^= (offl >> 3) & 0x30;
        *(uint4*)(sAc + offh) = make_uint4(hiw[0], hiw[1], hiw[2], hiw[3]);
        *(uint4*)(sAc + offl) = make_uint4(low[0], low[1], low[2], low[3]);
    }
    __syncthreads();

    // ---- main pipeline ----
    for (int chunk = 0; chunk < NCHUNK; chunk++) {
        int cb = chunk & 1, nb = cb ^ 1;
        int nk = (chunk + 1 < NCHUNK) ? chunk + 1 : 0;   // clamped (last iter redundant)
        int ncr0 = nk * CHC;

        // (1) prefetch next A floats into registers (LDGs fly during MMA)
        float va[4][8];
        #pragma unroll
        for (int g = 0; g < 4; g++) {
            int s = tid + g*256;
            if (s < 2*IPX) {
                int hh = s / IPX, p = s - hh*IPX;
                int row = p / 66, col = p - row*66;
                const float* xp = xb + (size_t)(ncr0 + hh*8) * NHW + (y0 + row)*NH + col;
                #pragma unroll
                for (int j = 0; j < 8; j++) va[g][j] = xp[(size_t)j * NHW];
            }
        }

        // (2) MMA taps on current buffer
        uint32_t abase = sA_u32 + (uint32_t)cb * ABUF_BYTES;
        const unsigned long long* bcur = sBb + cb*1728 + lane;
        #pragma unroll
        for (int tap = 0; tap < 9; tap++) {
            const int d = (tap/3)*66 + (tap%3);
            uint32_t o0 = pxoff[0] + (uint32_t)(d*64); o0 ^= (o0 >> 3) & 0x30;
            uint32_t o1 = pxoff[1] + (uint32_t)(d*64); o1 ^= (o1 >> 3) & 0x30;
            uint32_t a0 = abase + o0, a1 = abase + o1;
            uint32_t h00, h01, h02, h03, l00, l01, l02, l03;
            uint32_t h10, h11, h12, h13, l10, l11, l12, l13;
            LDSM_X4(h00, h01, h02, h03, a0);
            LDSM_X4(l00, l01, l02, l03, a0 ^ 32u);
            LDSM_X4(h10, h11, h12, h13, a1);
            LDSM_X4(l10, l11, l12, l13, a1 ^ 32u);
            const unsigned long long* bp = bcur + tap*192;
            #pragma unroll
            for (int nt = 0; nt < 6; nt++) {
                unsigned long long b2 = bp[nt*32];
                uint32_t b0 = (uint32_t)b2, b1 = (uint32_t)(b2 >> 32);
                MMA16816F16(acc[0][nt], h00, h01, h02, h03, b0, b1);
                MMA16816F16(acc[0][nt], l00, l01, l02, l03, b0, b1);
                MMA16816F16(acc[1][nt], h10, h11, h12, h13, b0, b1);
                MMA16816F16(acc[1][nt], l10, l11, l12, l13, b0, b1);
            }
        }

        // (3) copy next B into other buffer (L2-hot)
        {
            const uint4* bs = wbsrc + (size_t)nk * 864;
            uint4* bd = sB4 + nb*864;
            #pragma unroll
            for (int i = tid; i < 864; i += 256) bd[i] = bs[i];
        }

        // (4) convert prefetched A -> swizzled STS into other buffer
        #pragma unroll
        for (int g = 0; g < 4; g++) {
            int s = tid + g*256;
            if (s < 2*IPX) {
                int hh = s / IPX, p = s - hh*IPX;
                float sp = s_sp[p];
                uint32_t hiw[4], low[4];
                #pragma unroll
                for (int j = 0; j < 4; j++) {
                    int cra = ncr0 + hh*8 + 2*j;
                    float v0 = fmaxf(fmaf(s_ga[cra],     va[g][2*j],     s_gb[cra]),     0.f) * sp;
                    float v1 = fmaxf(fmaf(s_ga[cra + 1], va[g][2*j + 1], s_gb[cra + 1]), 0.f) * sp;
                    __half h0 = __float2half(v0), h1 = __float2half(v1);
                    __half l0 = __float2half(v0 - __half2float(h0));
                    __half l1 = __float2half(v1 - __half2float(h1));
                    hiw[j] = (uint32_t)__half_as_ushort(h0) | ((uint32_t)__half_as_ushort(h1) << 16);
                    low[j] = (uint32_t)__half_as_ushort(l0) | ((uint32_t)__half_as_ushort(l1) << 16);
                }
                uint32_t offh = (uint32_t)(p*64 + hh*16);       offh ^= (offh >> 3) & 0x30;
                uint32_t offl = (uint32_t)(p*64 + (hh + 2)*16); offl ^= (offl >> 3) & 0x30;
                char* dst = sAc + (size_t)nb * ABUF_BYTES;
                *(uint4*)(dst + offh) = make_uint4(hiw[0], hiw[1], hiw[2], hiw[3]);
                *(uint4*)(dst + offl) = make_uint4(low[0], low[1], low[2], low[3]);
            }
        }
        __syncthreads();
    }

    // epilogue
    #pragma unroll
    for (int t = 0; t < 2; t++) {
        int tt = 2*w + t;
        int ox = (tt & 3)*16 + (lane >> 2);
        int oy = y0 + (tt >> 2);
        #pragma unroll
        for (int nt = 0; nt < 6; nt++) {
            int o0 = nt*8 + (lane & 3)*2;
            size_t i0 = (((size_t)(b*144 + o0))*4 + h)*4096 + (size_t)oy*64;
            out[i0 + ox]               = acc[t][nt][0];
            out[i0 + 16384 + ox]       = acc[t][nt][1];
            out[i0 + ox + 8]           = acc[t][nt][2];
            out[i0 + 16384 + ox + 8]   = acc[t][nt][3];
        }
    }
}

// ---------------- L4: dense concat crop ----------------
__global__ void k_crop(const float* __restrict__ x, float* __restrict__ out) {
    int idx = blockIdx.x*256 + threadIdx.x;
    if (idx >= NB*NC*NR*64*16) return;
    int q   = idx & 15;
    int y   = (idx >> 4) & 63;
    int brc = idx >> 10;
    int b   = brc / NCR;
    int crr = brc % NCR;
    int c   = crr >> 2, r = crr & 3;
    const float* src = x + (size_t)brc * NHW + (size_t)(y + 1)*NH + (q*4 + 1);
    float4 v = make_float4(src[0], src[1], src[2], src[3]);
    size_t off = (((size_t)b*144 + 48 + c)*4 + r)*4096 + (size_t)y*64 + q*4;
    *(float4*)(out + off) = v;
}

// ---------------- launch ----------------
extern "C" void kernel_launch(void* const* d_in, const int* in_sizes, int n_in,
                              void* d_out, int out_size) {
    const float* x     = (const float*)d_in[0];
    const float* gamma = (const float*)d_in[1];
    const float* beta  = (const float*)d_in[2];
    const float* fc1   = (const float*)d_in[3];
    const float* fc2   = (const float*)d_in[4];
    const float* sa    = (const float*)d_in[5];
    const float* cw    = (const float*)d_in[6];
    float* out = (float*)d_out;
    (void)in_sizes; (void)n_in; (void)out_size;

    static int smem_set = 0;
    if (!smem_set) {
        cudaFuncSetAttribute(k_conv, cudaFuncAttributeMaxDynamicSharedMemorySize, CONV_DYN);
        smem_set = 1;
    }

    int init_blocks = 775 + (WB_TOTAL + 255)/256;
    k_init<<<init_blocks, 256>>>(x, cw, sa);                       // 0
    k_pool<<<NB*NCR + PB*NB*NR, 256>>>(x, gamma, beta);            // 1
    k_att <<<NB + PB*NB*NR, 256>>>(fc1, fc2);                      // 2
    k_conv<<<dim3(16, NB*NR), 256, CONV_DYN>>>(x, gamma, beta, out);  // 3  <- profiled
    k_crop<<<(NB*NC*NR*64*16 + 255)/256, 256>>>(x, out);           // 4
}